// round 13
// baseline (speedup 1.0000x reference)
#include <cuda_runtime.h>
#include <cuda_fp16.h>
#include <math.h>
#include <stdint.h>

#define DIM   768
#define HEADS 16
#define DK    48
#define B     2
#define S     2048
#define MROWS (B * S)          // 4096

// Scratch (static device globals — no runtime allocation)
__device__ __half g_q[B * HEADS * S * DK];    // fp16, pre-scaled (1/sqrt(dk))*log2(e)
__device__ __half g_k[B * HEADS * S * DK];    // fp16
__device__ __half g_v[B * HEADS * S * DK];    // fp16
__device__ __half g_ctx[MROWS * DIM];         // fp16 attention output

#define XC_ELEMS (MROWS * DIM)                // 3145728
#define WC_ELEMS (DIM * DIM)                  // 589824
__device__ __half g_cvt[XC_ELEMS + 4 * WC_ELEMS];  // fp16 x | Wq | Wk | Wv | Wo

// ---------------------------------------------------------------------------
// helpers
// ---------------------------------------------------------------------------
__device__ __forceinline__ uint32_t packh2(float lo, float hi) {
    __half2 h = __floats2half2_rn(lo, hi);
    return *reinterpret_cast<uint32_t*>(&h);
}

__device__ __forceinline__ uint32_t h2exp2(uint32_t x) {
    uint32_t r;
    asm("ex2.approx.f16x2 %0, %1;" : "=r"(r) : "r"(x));
    return r;
}

__device__ __forceinline__ void mma_f16(float c[4],
                                        const uint32_t a[4],
                                        const uint32_t b[2]) {
    asm volatile(
        "mma.sync.aligned.m16n8k16.row.col.f32.f16.f16.f32 "
        "{%0,%1,%2,%3}, {%4,%5,%6,%7}, {%8,%9}, {%0,%1,%2,%3};\n"
        : "+f"(c[0]), "+f"(c[1]), "+f"(c[2]), "+f"(c[3])
        : "r"(a[0]), "r"(a[1]), "r"(a[2]), "r"(a[3]),
          "r"(b[0]), "r"(b[1]));
}

__device__ __forceinline__ void ldsm_x4(uint32_t& r0, uint32_t& r1,
                                        uint32_t& r2, uint32_t& r3,
                                        uint32_t saddr) {
    asm volatile(
        "ldmatrix.sync.aligned.m8n8.x4.shared.b16 {%0,%1,%2,%3}, [%4];"
        : "=r"(r0), "=r"(r1), "=r"(r2), "=r"(r3) : "r"(saddr));
}

__device__ __forceinline__ void ldsm_x4_trans(uint32_t& r0, uint32_t& r1,
                                              uint32_t& r2, uint32_t& r3,
                                              uint32_t saddr) {
    asm volatile(
        "ldmatrix.sync.aligned.m8n8.x4.trans.shared.b16 {%0,%1,%2,%3}, [%4];"
        : "=r"(r0), "=r"(r1), "=r"(r2), "=r"(r3) : "r"(saddr));
}

__device__ __forceinline__ void cp_async16(uint32_t saddr, const void* gptr) {
    asm volatile("cp.async.cg.shared.global [%0], [%1], 16;"
                 :: "r"(saddr), "l"(gptr));
}
__device__ __forceinline__ void cp_commit() {
    asm volatile("cp.async.commit_group;");
}
template <int N>
__device__ __forceinline__ void cp_wait() {
    asm volatile("cp.async.wait_group %0;" :: "n"(N));
}

// ---------------------------------------------------------------------------
// Elementwise fp16 pre-conversion: x, Wq, Wk, Wv, Wo -> g_cvt
// ---------------------------------------------------------------------------
__global__ __launch_bounds__(256)
void convert_f16_kernel(const float* __restrict__ x,
                        const float* __restrict__ Wq,
                        const float* __restrict__ Wk,
                        const float* __restrict__ Wv,
                        const float* __restrict__ Wo,
                        uint32_t* __restrict__ out)
{
    const int total8 = (XC_ELEMS + 4 * WC_ELEMS) / 8;
    for (int i = blockIdx.x * blockDim.x + threadIdx.x; i < total8;
         i += gridDim.x * blockDim.x) {
        const int e = i * 8;
        const float* src;
        if (e < XC_ELEMS) {
            src = x + e;
        } else {
            const int r = e - XC_ELEMS;
            const int w = r / WC_ELEMS;
            const int off = r % WC_ELEMS;
            src = (w == 0 ? Wq : w == 1 ? Wk : w == 2 ? Wv : Wo) + off;
        }
        float4 v0 = *(const float4*)src;
        float4 v1 = *(const float4*)(src + 4);
        uint4 u;
        u.x = packh2(v0.x, v0.y);
        u.y = packh2(v0.z, v0.w);
        u.z = packh2(v1.x, v1.y);
        u.w = packh2(v1.z, v1.w);
        *(uint4*)(out + e / 2) = u;
    }
}

// ---------------------------------------------------------------------------
// Pipelined fp16 tensor-core GEMM: out = A[M,K] @ W[N,K]^T + bias[N]
// Block tile 128x64, BK=64 halfs (4 k16 steps per slab -> 12 slabs, 12
// barriers instead of 24). 3-stage cp.async ring (same bytes in flight as
// the old 4x32 ring). Pitch 72 halfs (9 x 16B granules, odd -> conflict-free).
// FUSED=true : blockIdx.x/12 -> segment 0:q(*qscale) 1:k 2:v, fp16 scatter
//              to [B,HEADS,S,DK].
// FUSED=false: plain fp32 out [M,N].
// ---------------------------------------------------------------------------
#define BKH 64
#define APH 72
#define A_BYTES (128 * APH * 2)      // 18432
#define B_BYTES (64 * APH * 2)       // 9216
#define NSTAGE 3
#define GEMM_SMEM_BYTES (NSTAGE * (A_BYTES + B_BYTES))   // 82944

template <bool FUSED>
__global__ __launch_bounds__(256)
void gemm_pipe_kernel(const __half* __restrict__ A,
                      const __half* __restrict__ W0, const float* __restrict__ b0,
                      void* __restrict__ o0,
                      const __half* __restrict__ W1, const float* __restrict__ b1,
                      void* __restrict__ o1,
                      const __half* __restrict__ W2, const float* __restrict__ b2,
                      void* __restrict__ o2,
                      int M, int N, int K, float qscale)
{
    extern __shared__ uint32_t smem[];

    const int tid  = threadIdx.x;
    const int lane = tid & 31;
    const int warp = tid >> 5;
    const int warpM = warp >> 1;
    const int warpN = warp & 1;
    const int g   = lane >> 2;
    const int tig = lane & 3;
    const int mi  = lane >> 3;
    const int ri  = lane & 7;

    int seg = 0, bnx = blockIdx.x;
    const __half* W = W0; const float* bias = b0; void* out = o0;
    if (FUSED) {
        seg = blockIdx.x / 12;
        bnx = blockIdx.x % 12;
        if (seg == 1)      { W = W1; bias = b1; out = o1; }
        else if (seg == 2) { W = W2; bias = b2; out = o2; }
    }

    const int bm = blockIdx.y * 128;
    const int bn = bnx * 64;

    const int lrA = tid >> 1;                // 0..127
    const int lkA = (tid & 1) * 32;          // 0 / 32 (halfs)
    const int lrB = tid >> 2;                // 0..63
    const int lkB = (tid & 3) * 16;          // 0/16/32/48 (halfs)

    const __half* Aptr = A + (size_t)(bm + lrA) * K + lkA;
    const __half* Wptr = W + (size_t)(bn + lrB) * K + lkB;

    const int arow = warpM * 32;
    const int bcol = warpN * 32;

    const uint32_t as_sb = (uint32_t)__cvta_generic_to_shared(smem);
    const uint32_t bs_sb = as_sb + NSTAGE * A_BYTES;
    // A frag: row = arow + mt*16 + (mi&1)*8 + ri, kcol = ks*16 + (mi>>1)*8
    const uint32_t aaddr0 = as_sb +
        ((arow + (mi & 1) * 8 + ri) * APH + (mi >> 1) * 8) * 2;
    // B frag: nrow = bcol + p*16 + (mi>>1)*8 + ri, kcol = ks*16 + (mi&1)*8
    const uint32_t baddr0 = bs_sb +
        ((bcol + (mi >> 1) * 8 + ri) * APH + (mi & 1) * 8) * 2;

    auto stage = [&](int s, int buf) {
        const __half* ap = Aptr + s * BKH;
        #pragma unroll
        for (int i = 0; i < 4; i++)
            cp_async16(as_sb + (uint32_t)buf * A_BYTES +
                           (lrA * APH + lkA + i * 8) * 2,
                       ap + i * 8);
        const __half* wp = Wptr + s * BKH;
        #pragma unroll
        for (int i = 0; i < 2; i++)
            cp_async16(bs_sb + (uint32_t)buf * B_BYTES +
                           (lrB * APH + lkB + i * 8) * 2,
                       wp + i * 8);
    };

    float c[2][4][4];
    #pragma unroll
    for (int mt = 0; mt < 2; mt++)
        #pragma unroll
        for (int nt = 0; nt < 4; nt++)
            #pragma unroll
            for (int i = 0; i < 4; i++) c[mt][nt][i] = 0.0f;

    const int NS = K / BKH;      // 12 slabs
    stage(0, 0); cp_commit();
    stage(1, 1); cp_commit();

    for (int s = 0; s < NS; s++) {
        if (s + 1 < NS) cp_wait<1>();
        else            cp_wait<0>();
        __syncthreads();
        if (s + 2 < NS) { stage(s + 2, (s + 2) % NSTAGE); cp_commit(); }

        const int buf = s % NSTAGE;
        const uint32_t abuf = aaddr0 + (uint32_t)buf * A_BYTES;
        const uint32_t bbuf = baddr0 + (uint32_t)buf * B_BYTES;
        #pragma unroll
        for (int ks = 0; ks < 4; ks++) {
            const uint32_t koff = ks * 32;           // 16 halfs
            uint32_t afr[2][4], bfr[4][2];
            #pragma unroll
            for (int mt = 0; mt < 2; mt++)
                ldsm_x4(afr[mt][0], afr[mt][1], afr[mt][2], afr[mt][3],
                        abuf + mt * (16 * APH * 2) + koff);
            #pragma unroll
            for (int p = 0; p < 2; p++)
                ldsm_x4(bfr[2*p][0], bfr[2*p][1], bfr[2*p+1][0], bfr[2*p+1][1],
                        bbuf + p * (16 * APH * 2) + koff);
            #pragma unroll
            for (int mt = 0; mt < 2; mt++)
                #pragma unroll
                for (int nt = 0; nt < 4; nt++)
                    mma_f16(c[mt][nt], afr[mt], bfr[nt]);
        }
    }

    // ---- epilogue ----
    #pragma unroll
    for (int mt = 0; mt < 2; mt++) {
        #pragma unroll
        for (int nt = 0; nt < 4; nt++) {
            #pragma unroll
            for (int i = 0; i < 4; i++) {
                const int m = bm + arow + mt * 16 + g + (i >> 1) * 8;
                const int n = bn + bcol + nt * 8 + 2 * tig + (i & 1);
                const float v = c[mt][nt][i] + bias[n];
                if (!FUSED) {
                    ((float*)out)[(size_t)m * N + n] = v;
                } else {
                    const int bidx = m / S;
                    const int s_   = m % S;
                    const int h    = n / DK;
                    const int d    = n % DK;
                    const size_t idx = (((size_t)bidx * HEADS + h) * S + s_) * DK + d;
                    const float sv = (seg == 0) ? v * qscale : v;
                    ((__half*)out)[idx] = __float2half_rn(sv);
                }
            }
        }
    }
}

// ---------------------------------------------------------------------------
// fp16 tensor-core flash attention, softmax-lite:
//   - Q pre-scaled by (1/sqrt(dk))*log2(e) -> scores in log2 domain
//   - P = ex2.approx.f16x2 of packed (s - m): ONE MUFU per score pair,
//     output directly in fp16 mma A-operand form (no separate pack)
//   - ones-column trick: V smem col 48 = 1.0 (cols 49-55 = 0), a 7th PV
//     n-tile accumulates row-sums (lrun) inside the mma with exact online
//     rescaling -> no lrun FADD chains, no epilogue shfl reductions.
// ---------------------------------------------------------------------------
#define KPH 56
#define PPH 56
#define VHP 56
#define KB_BYTES (64 * KPH * 2)      // 7168
#define VB_BYTES (64 * VHP * 2)      // 7168
#define PS_BYTES (128 * PPH * 2)     // 14336
#define ATT_SMEM_BYTES (2 * KB_BYTES + 2 * VB_BYTES + PS_BYTES)   // 43008

__global__ __launch_bounds__(256)
void attention_mma_kernel(const __half* __restrict__ Q,
                          const __half* __restrict__ K,
                          const __half* __restrict__ Vf,
                          __half* __restrict__ ctx)
{
    extern __shared__ uint32_t sm[];

    const int qt   = blockIdx.x;
    const int h    = blockIdx.y;
    const int b    = blockIdx.z;
    const int tid  = threadIdx.x;
    const int lane = tid & 31;
    const int warp = tid >> 5;
    const int g    = lane >> 2;
    const int tig  = lane & 3;
    const int mi   = lane >> 3;
    const int ri   = lane & 7;
    const int r0   = warp * 16;

    const size_t head_off = ((size_t)b * HEADS + h) * S * DK;

    const uint32_t base_sb = (uint32_t)__cvta_generic_to_shared(sm);
    const uint32_t ks_sb = base_sb;
    const uint32_t vh_sb = base_sb + 2 * KB_BYTES;
    const uint32_t ps_sb = base_sb + 2 * KB_BYTES + 2 * VB_BYTES;
    __half* Vsh = (__half*)((char*)sm + 2 * KB_BYTES);
    __half* Psh = (__half*)((char*)sm + 2 * KB_BYTES + 2 * VB_BYTES);

    const uint32_t kaddr = ks_sb + (((mi >> 1) * 8 + ri) * KPH + (mi & 1) * 8) * 2;
    const uint32_t paddr = ps_sb + ((r0 + (mi & 1) * 8 + ri) * PPH + (mi >> 1) * 8) * 2;
    const uint32_t vaddr = vh_sb + (((mi & 1) * 8 + ri) * VHP + (mi >> 1) * 8) * 2;

    const __half* kg = K + head_off;
    const __half* vg = Vf + head_off;

    auto stage_tile = [&](int kt, int bufsel) {
        const __half* ksrc = kg + (size_t)kt * 64 * DK;
        #pragma unroll
        for (int i = tid; i < 384; i += 256) {
            const int row = i / 6, c8 = (i % 6) * 8;
            cp_async16(ks_sb + (uint32_t)bufsel * KB_BYTES + (row * KPH + c8) * 2,
                       ksrc + row * DK + c8);
        }
        const __half* vsrc = vg + (size_t)kt * 64 * DK;
        #pragma unroll
        for (int i = tid; i < 384; i += 256) {
            const int row = i / 6, c8 = (i % 6) * 8;
            cp_async16(vh_sb + (uint32_t)bufsel * VB_BYTES + (row * VHP + c8) * 2,
                       vsrc + row * DK + c8);
        }
    };

    stage_tile(0, 0);
    cp_commit();

    // ---- stage Q tile + write ones-column into V smem (cols 48..55,
    //      never touched by cp.async -> persists across all tiles) ----
    {
        const uint4* qsrc = (const uint4*)(Q + head_off + (size_t)qt * 128 * DK);
        #pragma unroll
        for (int i = tid; i < 768; i += 256) {
            const int row = i / 6, c8 = (i % 6) * 8;
            *(uint4*)&Psh[row * PPH + c8] = qsrc[i];
        }
        if (tid < 128) {
            const int bsel = tid >> 6, row = tid & 63;
            uint4 ones = { 0x00003C00u, 0u, 0u, 0u };   // {1.0h, 0...}
            *(uint4*)&Vsh[bsel * (VB_BYTES / 2) + row * VHP + 48] = ones;
        }
    }
    __syncthreads();

    // ---- Q fragments -> registers via ldmatrix ----
    uint32_t qf[3][4];
    #pragma unroll
    for (int ks = 0; ks < 3; ks++)
        ldsm_x4(qf[ks][0], qf[ks][1], qf[ks][2], qf[ks][3], paddr + ks * 32);

    float ctxa[7][4];                  // [0..5]: dk cols; [6]: row-sum column
    #pragma unroll
    for (int nt = 0; nt < 7; nt++)
        #pragma unroll
        for (int i = 0; i < 4; i++) ctxa[nt][i] = 0.0f;
    float mrun0 = -INFINITY, mrun1 = -INFINITY;

    const int NT = S / 64;
    for (int kt = 0; kt < NT; kt++) {
        const int buf = kt & 1;

        if (kt + 1 < NT) {
            stage_tile(kt + 1, buf ^ 1);
            cp_commit();
            cp_wait<1>();
        } else {
            cp_wait<0>();
        }
        __syncthreads();

        const uint32_t kbuf = kaddr + (uint32_t)buf * KB_BYTES;
        const uint32_t vbuf = vaddr + (uint32_t)buf * VB_BYTES;

        // ---- scores = Q @ K^T (fp16 mma, log2-domain) ----
        float sc[8][4];
        #pragma unroll
        for (int nt = 0; nt < 8; nt++)
            #pragma unroll
            for (int i = 0; i < 4; i++) sc[nt][i] = 0.0f;

        #pragma unroll
        for (int ks = 0; ks < 3; ks++) {
            const uint32_t ka = kbuf + ks * 32;
            #pragma unroll
            for (int p = 0; p < 4; p++) {
                uint32_t b0, b1, b2, b3;
                ldsm_x4(b0, b1, b2, b3, ka + p * (16 * KPH * 2));
                uint32_t f0[2] = { b0, b1 };
                uint32_t f1[2] = { b2, b3 };
                mma_f16(sc[2 * p],     qf[ks], f0);
                mma_f16(sc[2 * p + 1], qf[ks], f1);
            }
        }

        // ---- online max (register + shfl; rows warp-local) ----
        float m0 = sc[0][0], m1 = sc[0][2];
        #pragma unroll
        for (int nt = 0; nt < 8; nt++) {
            m0 = fmaxf(m0, fmaxf(sc[nt][0], sc[nt][1]));
            m1 = fmaxf(m1, fmaxf(sc[nt][2], sc[nt][3]));
        }
        m0 = fmaxf(m0, __shfl_xor_sync(0xFFFFFFFF, m0, 1));
        m0 = fmaxf(m0, __shfl_xor_sync(0xFFFFFFFF, m0, 2));
        m1 = fmaxf(m1, __shfl_xor_sync(0xFFFFFFFF, m1, 1));
        m1 = fmaxf(m1, __shfl_xor_sync(0xFFFFFFFF, m1, 2));

        const float mn0 = fmaxf(mrun0, m0);
        const float mn1 = fmaxf(mrun1, m1);
        const float corr0 = exp2f(mrun0 - mn0);   // exp2(-inf)=0 first time
        const float corr1 = exp2f(mrun1 - mn1);
        mrun0 = mn0; mrun1 = mn1;
        #pragma unroll
        for (int nt = 0; nt < 7; nt++) {
            ctxa[nt][0] *= corr0; ctxa[nt][1] *= corr0;
            ctxa[nt][2] *= corr1; ctxa[nt][3] *= corr1;
        }

        // ---- ctx (+rowsum col) += P @ V; P = ex2.f16x2(s - m) on the fly ----
        #pragma unroll
        for (int ck = 0; ck < 4; ck++) {
            uint32_t pa[4];
            pa[0] = h2exp2(packh2(sc[2*ck][0]   - mn0, sc[2*ck][1]   - mn0));
            pa[1] = h2exp2(packh2(sc[2*ck][2]   - mn1, sc[2*ck][3]   - mn1));
            pa[2] = h2exp2(packh2(sc[2*ck+1][0] - mn0, sc[2*ck+1][1] - mn0));
            pa[3] = h2exp2(packh2(sc[2*ck+1][2] - mn1, sc[2*ck+1][3] - mn1));
            const uint32_t vck = vbuf + ck * (16 * VHP * 2);
            #pragma unroll
            for (int t = 0; t < 3; t++) {
                uint32_t b0, b1, b2, b3;
                ldsm_x4_trans(b0, b1, b2, b3, vck + t * 32);
                uint32_t f0[2] = { b0, b1 };
                uint32_t f1[2] = { b2, b3 };
                mma_f16(ctxa[2 * t],     pa, f0);
                mma_f16(ctxa[2 * t + 1], pa, f1);
            }
            // 7th n-tile: cols 48-55 (col 48 = ones -> row sums)
            {
                uint32_t b0, b1, b2, b3;
                ldsm_x4_trans(b0, b1, b2, b3, vck + 3 * 32);
                uint32_t f0[2] = { b0, b1 };
                mma_f16(ctxa[6], pa, f0);
            }
        }
        __syncthreads();
    }

    // ---- epilogue: lrun = ctx col 48 (broadcast within 4-lane group) ----
    const float l0 = __shfl_sync(0xFFFFFFFF, ctxa[6][0], lane & 28);
    const float l1 = __shfl_sync(0xFFFFFFFF, ctxa[6][2], lane & 28);
    const float inv0 = 1.0f / l0;
    const float inv1 = 1.0f / l1;

    const int srow0 = qt * 128 + r0 + g;
    __half* out0 = ctx + ((size_t)b * S + srow0)     * DIM + h * DK;
    __half* out1 = ctx + ((size_t)b * S + srow0 + 8) * DIM + h * DK;
    #pragma unroll
    for (int nt = 0; nt < 6; nt++) {
        const int col = nt * 8 + 2 * tig;
        *(uint32_t*)(out0 + col) = packh2(ctxa[nt][0] * inv0, ctxa[nt][1] * inv0);
        *(uint32_t*)(out1 + col) = packh2(ctxa[nt][2] * inv1, ctxa[nt][3] * inv1);
    }
}

// ---------------------------------------------------------------------------
extern "C" void kernel_launch(void* const* d_in, const int* in_sizes, int n_in,
                              void* d_out, int out_size)
{
    const float* x  = (const float*)d_in[0];
    const float* Wq = (const float*)d_in[1];
    const float* bq = (const float*)d_in[2];
    const float* Wk = (const float*)d_in[3];
    const float* bk = (const float*)d_in[4];
    const float* Wv = (const float*)d_in[5];
    const float* bv = (const float*)d_in[6];
    const float* Wo = (const float*)d_in[7];
    const float* bo = (const float*)d_in[8];
    float* out = (float*)d_out;

    __half *q, *k, *v, *ctx, *cvt;
    cudaGetSymbolAddress((void**)&q,   g_q);
    cudaGetSymbolAddress((void**)&k,   g_k);
    cudaGetSymbolAddress((void**)&v,   g_v);
    cudaGetSymbolAddress((void**)&ctx, g_ctx);
    cudaGetSymbolAddress((void**)&cvt, g_cvt);

    const __half* xc  = cvt;
    const __half* Wqc = cvt + XC_ELEMS;
    const __half* Wkc = cvt + XC_ELEMS + WC_ELEMS;
    const __half* Wvc = cvt + XC_ELEMS + 2 * WC_ELEMS;
    const __half* Woc = cvt + XC_ELEMS + 3 * WC_ELEMS;

    cudaFuncSetAttribute(gemm_pipe_kernel<true>,
                         cudaFuncAttributeMaxDynamicSharedMemorySize, GEMM_SMEM_BYTES);
    cudaFuncSetAttribute(gemm_pipe_kernel<false>,
                         cudaFuncAttributeMaxDynamicSharedMemorySize, GEMM_SMEM_BYTES);
    cudaFuncSetAttribute(attention_mma_kernel,
                         cudaFuncAttributeMaxDynamicSharedMemorySize, ATT_SMEM_BYTES);

    // (1/sqrt(48)) * log2(e): scores emerge in log2 domain
    const float qscale = 0.14433756729740643f * 1.4426950408889634f;

    // Pre-convert x + all weights to fp16
    convert_f16_kernel<<<1184, 256>>>(x, Wq, Wk, Wv, Wo, (uint32_t*)cvt);

    // Fused Q/K/V projections: one launch, 36x32 = 1152 blocks
    dim3 qkv_grid(36, MROWS / 128);
    gemm_pipe_kernel<true><<<qkv_grid, 256, GEMM_SMEM_BYTES>>>(
        xc, Wqc, bq, q, Wkc, bk, k, Wvc, bv, v, MROWS, DIM, DIM, qscale);

    // Attention
    dim3 agrd(S / 128, HEADS, B);                // (16, 16, 2)
    attention_mma_kernel<<<agrd, 256, ATT_SMEM_BYTES>>>(q, k, v, ctx);

    // Output projection
    dim3 o_grid(DIM / 64, MROWS / 128);          // (12, 32)
    gemm_pipe_kernel<false><<<o_grid, 256, GEMM_SMEM_BYTES>>>(
        ctx, Woc, bo, out, nullptr, nullptr, nullptr,
        nullptr, nullptr, nullptr, MROWS, DIM, DIM, 1.0f);
}

// round 14
// speedup vs baseline: 1.0796x; 1.0796x over previous
#include <cuda_runtime.h>
#include <cuda_fp16.h>
#include <math.h>
#include <stdint.h>

#define DIM   768
#define HEADS 16
#define DK    48
#define B     2
#define S     2048
#define MROWS (B * S)          // 4096

// Scratch (static device globals — no runtime allocation)
__device__ __half g_q[B * HEADS * S * DK];    // fp16, pre-scaled (1/sqrt(dk))*log2(e)
__device__ __half g_k[B * HEADS * S * DK];    // fp16
__device__ __half g_v[B * HEADS * S * DK];    // fp16
__device__ __half g_ctx[MROWS * DIM];         // fp16 attention output

#define XC_ELEMS (MROWS * DIM)                // 3145728
#define WC_ELEMS (DIM * DIM)                  // 589824
__device__ __half g_cvt[XC_ELEMS + 4 * WC_ELEMS];  // fp16 x | Wq | Wk | Wv | Wo

// ---------------------------------------------------------------------------
// helpers
// ---------------------------------------------------------------------------
__device__ __forceinline__ uint32_t packh2(float lo, float hi) {
    __half2 h = __floats2half2_rn(lo, hi);
    return *reinterpret_cast<uint32_t*>(&h);
}

__device__ __forceinline__ uint32_t h2exp2(uint32_t x) {
    uint32_t r;
    asm("ex2.approx.f16x2 %0, %1;" : "=r"(r) : "r"(x));
    return r;
}

__device__ __forceinline__ void mma_f16(float c[4],
                                        const uint32_t a[4],
                                        const uint32_t b[2]) {
    asm volatile(
        "mma.sync.aligned.m16n8k16.row.col.f32.f16.f16.f32 "
        "{%0,%1,%2,%3}, {%4,%5,%6,%7}, {%8,%9}, {%0,%1,%2,%3};\n"
        : "+f"(c[0]), "+f"(c[1]), "+f"(c[2]), "+f"(c[3])
        : "r"(a[0]), "r"(a[1]), "r"(a[2]), "r"(a[3]),
          "r"(b[0]), "r"(b[1]));
}

__device__ __forceinline__ void ldsm_x4(uint32_t& r0, uint32_t& r1,
                                        uint32_t& r2, uint32_t& r3,
                                        uint32_t saddr) {
    asm volatile(
        "ldmatrix.sync.aligned.m8n8.x4.shared.b16 {%0,%1,%2,%3}, [%4];"
        : "=r"(r0), "=r"(r1), "=r"(r2), "=r"(r3) : "r"(saddr));
}

__device__ __forceinline__ void ldsm_x4_trans(uint32_t& r0, uint32_t& r1,
                                              uint32_t& r2, uint32_t& r3,
                                              uint32_t saddr) {
    asm volatile(
        "ldmatrix.sync.aligned.m8n8.x4.trans.shared.b16 {%0,%1,%2,%3}, [%4];"
        : "=r"(r0), "=r"(r1), "=r"(r2), "=r"(r3) : "r"(saddr));
}

__device__ __forceinline__ void cp_async16(uint32_t saddr, const void* gptr) {
    asm volatile("cp.async.cg.shared.global [%0], [%1], 16;"
                 :: "r"(saddr), "l"(gptr));
}
__device__ __forceinline__ void cp_commit() {
    asm volatile("cp.async.commit_group;");
}
template <int N>
__device__ __forceinline__ void cp_wait() {
    asm volatile("cp.async.wait_group %0;" :: "n"(N));
}

// ---------------------------------------------------------------------------
// Elementwise fp16 pre-conversion: x, Wq, Wk, Wv, Wo -> g_cvt
// ---------------------------------------------------------------------------
__global__ __launch_bounds__(256)
void convert_f16_kernel(const float* __restrict__ x,
                        const float* __restrict__ Wq,
                        const float* __restrict__ Wk,
                        const float* __restrict__ Wv,
                        const float* __restrict__ Wo,
                        uint32_t* __restrict__ out)
{
    const int total8 = (XC_ELEMS + 4 * WC_ELEMS) / 8;
    for (int i = blockIdx.x * blockDim.x + threadIdx.x; i < total8;
         i += gridDim.x * blockDim.x) {
        const int e = i * 8;
        const float* src;
        if (e < XC_ELEMS) {
            src = x + e;
        } else {
            const int r = e - XC_ELEMS;
            const int w = r / WC_ELEMS;
            const int off = r % WC_ELEMS;
            src = (w == 0 ? Wq : w == 1 ? Wk : w == 2 ? Wv : Wo) + off;
        }
        float4 v0 = *(const float4*)src;
        float4 v1 = *(const float4*)(src + 4);
        uint4 u;
        u.x = packh2(v0.x, v0.y);
        u.y = packh2(v0.z, v0.w);
        u.z = packh2(v1.x, v1.y);
        u.w = packh2(v1.z, v1.w);
        *(uint4*)(out + e / 2) = u;
    }
}

// ---------------------------------------------------------------------------
// Pipelined fp16 tensor-core GEMM (round-12 config, measured best):
// out = A[M,K] @ W[N,K]^T + bias[N], fp16 in, fp32 accum, mma.m16n8k16.
// Block tile 128x64, BK=32 halfs, 8 warps as 4x2. 4-stage cp.async ring,
// prefetch depth 2, one __syncthreads per slab. Pitch 40 halfs. 61440B smem
// -> 3 CTAs/SM.
// FUSED=true : blockIdx.x/12 -> segment 0:q(*qscale) 1:k 2:v, fp16 scatter.
// FUSED=false: plain fp32 out [M,N].
// ---------------------------------------------------------------------------
#define BKH 32
#define APH 40
#define A_BYTES (128 * APH * 2)      // 10240
#define B_BYTES (64 * APH * 2)       // 5120
#define NSTAGE 4
#define GEMM_SMEM_BYTES (NSTAGE * (A_BYTES + B_BYTES))   // 61440

template <bool FUSED>
__global__ __launch_bounds__(256)
void gemm_pipe_kernel(const __half* __restrict__ A,
                      const __half* __restrict__ W0, const float* __restrict__ b0,
                      void* __restrict__ o0,
                      const __half* __restrict__ W1, const float* __restrict__ b1,
                      void* __restrict__ o1,
                      const __half* __restrict__ W2, const float* __restrict__ b2,
                      void* __restrict__ o2,
                      int M, int N, int K, float qscale)
{
    extern __shared__ uint32_t smem[];

    const int tid  = threadIdx.x;
    const int lane = tid & 31;
    const int warp = tid >> 5;
    const int warpM = warp >> 1;
    const int warpN = warp & 1;
    const int g   = lane >> 2;
    const int tig = lane & 3;
    const int mi  = lane >> 3;
    const int ri  = lane & 7;

    int seg = 0, bnx = blockIdx.x;
    const __half* W = W0; const float* bias = b0; void* out = o0;
    if (FUSED) {
        seg = blockIdx.x / 12;
        bnx = blockIdx.x % 12;
        if (seg == 1)      { W = W1; bias = b1; out = o1; }
        else if (seg == 2) { W = W2; bias = b2; out = o2; }
    }

    const int bm = blockIdx.y * 128;
    const int bn = bnx * 64;

    const int lrA = tid >> 1;                // 0..127
    const int lkA = (tid & 1) * 16;          // 0 / 16 (halfs)
    const int lrB = tid >> 2;                // 0..63
    const int lkB = (tid & 3) * 8;           // 0/8/16/24 (halfs)

    const __half* Aptr = A + (size_t)(bm + lrA) * K + lkA;
    const __half* Wptr = W + (size_t)(bn + lrB) * K + lkB;

    const int arow = warpM * 32;
    const int bcol = warpN * 32;

    const uint32_t as_sb = (uint32_t)__cvta_generic_to_shared(smem);
    const uint32_t bs_sb = as_sb + NSTAGE * A_BYTES;
    const uint32_t aaddr0 = as_sb +
        ((arow + (mi & 1) * 8 + ri) * APH + (mi >> 1) * 8) * 2;
    const uint32_t baddr0 = bs_sb +
        ((bcol + (mi >> 1) * 8 + ri) * APH + (mi & 1) * 8) * 2;

    auto stage = [&](int s, int buf) {
        const __half* ap = Aptr + s * BKH;
        #pragma unroll
        for (int i = 0; i < 2; i++)
            cp_async16(as_sb + (uint32_t)buf * A_BYTES +
                           (lrA * APH + lkA + i * 8) * 2,
                       ap + i * 8);
        const __half* wp = Wptr + s * BKH;
        cp_async16(bs_sb + (uint32_t)buf * B_BYTES + (lrB * APH + lkB) * 2, wp);
    };

    float c[2][4][4];
    #pragma unroll
    for (int mt = 0; mt < 2; mt++)
        #pragma unroll
        for (int nt = 0; nt < 4; nt++)
            #pragma unroll
            for (int i = 0; i < 4; i++) c[mt][nt][i] = 0.0f;

    const int NS = K / BKH;      // 24 slabs
    stage(0, 0); cp_commit();
    stage(1, 1); cp_commit();
    stage(2, 2); cp_commit();

    for (int s = 0; s < NS; s++) {
        if (s + 2 < NS)      cp_wait<2>();
        else if (s + 1 < NS) cp_wait<1>();
        else                 cp_wait<0>();
        __syncthreads();
        if (s + 3 < NS) { stage(s + 3, (s + 3) & 3); cp_commit(); }

        const int buf = s & 3;
        const uint32_t abuf = aaddr0 + (uint32_t)buf * A_BYTES;
        const uint32_t bbuf = baddr0 + (uint32_t)buf * B_BYTES;
        #pragma unroll
        for (int ks = 0; ks < 2; ks++) {
            const uint32_t koff = ks * 32;           // 16 halfs
            uint32_t afr[2][4], bfr[4][2];
            #pragma unroll
            for (int mt = 0; mt < 2; mt++)
                ldsm_x4(afr[mt][0], afr[mt][1], afr[mt][2], afr[mt][3],
                        abuf + mt * (16 * APH * 2) + koff);
            #pragma unroll
            for (int p = 0; p < 2; p++)
                ldsm_x4(bfr[2*p][0], bfr[2*p][1], bfr[2*p+1][0], bfr[2*p+1][1],
                        bbuf + p * (16 * APH * 2) + koff);
            #pragma unroll
            for (int mt = 0; mt < 2; mt++)
                #pragma unroll
                for (int nt = 0; nt < 4; nt++)
                    mma_f16(c[mt][nt], afr[mt], bfr[nt]);
        }
    }

    // ---- epilogue ----
    #pragma unroll
    for (int mt = 0; mt < 2; mt++) {
        #pragma unroll
        for (int nt = 0; nt < 4; nt++) {
            #pragma unroll
            for (int i = 0; i < 4; i++) {
                const int m = bm + arow + mt * 16 + g + (i >> 1) * 8;
                const int n = bn + bcol + nt * 8 + 2 * tig + (i & 1);
                const float v = c[mt][nt][i] + bias[n];
                if (!FUSED) {
                    ((float*)out)[(size_t)m * N + n] = v;
                } else {
                    const int bidx = m / S;
                    const int s_   = m % S;
                    const int h    = n / DK;
                    const int d    = n % DK;
                    const size_t idx = (((size_t)bidx * HEADS + h) * S + s_) * DK + d;
                    const float sv = (seg == 0) ? v * qscale : v;
                    ((__half*)out)[idx] = __float2half_rn(sv);
                }
            }
        }
    }
}

// ---------------------------------------------------------------------------
// fp16 tensor-core flash attention, softmax-lite, 3-buffer K/V ring with a
// SINGLE __syncthreads per KV tile (buffer (kt+1)%3 never collides with
// stragglers reading (kt-1)%3 — indices differ by 2 mod 3):
//   - Q pre-scaled by (1/sqrt(dk))*log2(e) -> scores in log2 domain
//   - P = ex2.approx.f16x2 of packed (s - m), directly in mma A form
//   - ones-column trick: V smem col 48 = 1.0 -> 7th PV n-tile accumulates
//     row sums inside the mma (no lrun FADDs, no epilogue reductions)
// ---------------------------------------------------------------------------
#define KPH 56
#define PPH 56
#define VHP 56
#define KB_BYTES (64 * KPH * 2)      // 7168
#define VB_BYTES (64 * VHP * 2)      // 7168
#define PS_BYTES (128 * PPH * 2)     // 14336
#define NBUF 3
#define ATT_SMEM_BYTES (NBUF * (KB_BYTES + VB_BYTES) + PS_BYTES)   // 57344

__global__ __launch_bounds__(256)
void attention_mma_kernel(const __half* __restrict__ Q,
                          const __half* __restrict__ K,
                          const __half* __restrict__ Vf,
                          __half* __restrict__ ctx)
{
    extern __shared__ uint32_t sm[];

    const int qt   = blockIdx.x;
    const int h    = blockIdx.y;
    const int b    = blockIdx.z;
    const int tid  = threadIdx.x;
    const int lane = tid & 31;
    const int warp = tid >> 5;
    const int g    = lane >> 2;
    const int tig  = lane & 3;
    const int mi   = lane >> 3;
    const int ri   = lane & 7;
    const int r0   = warp * 16;

    const size_t head_off = ((size_t)b * HEADS + h) * S * DK;

    const uint32_t base_sb = (uint32_t)__cvta_generic_to_shared(sm);
    const uint32_t ks_sb = base_sb;
    const uint32_t vh_sb = base_sb + NBUF * KB_BYTES;
    const uint32_t ps_sb = base_sb + NBUF * (KB_BYTES + VB_BYTES);
    __half* Vsh = (__half*)((char*)sm + NBUF * KB_BYTES);
    __half* Psh = (__half*)((char*)sm + NBUF * (KB_BYTES + VB_BYTES));

    const uint32_t kaddr = ks_sb + (((mi >> 1) * 8 + ri) * KPH + (mi & 1) * 8) * 2;
    const uint32_t paddr = ps_sb + ((r0 + (mi & 1) * 8 + ri) * PPH + (mi >> 1) * 8) * 2;
    const uint32_t vaddr = vh_sb + (((mi & 1) * 8 + ri) * VHP + (mi >> 1) * 8) * 2;

    const __half* kg = K + head_off;
    const __half* vg = Vf + head_off;

    auto stage_tile = [&](int kt, int bufsel) {
        const __half* ksrc = kg + (size_t)kt * 64 * DK;
        #pragma unroll
        for (int i = tid; i < 384; i += 256) {
            const int row = i / 6, c8 = (i % 6) * 8;
            cp_async16(ks_sb + (uint32_t)bufsel * KB_BYTES + (row * KPH + c8) * 2,
                       ksrc + row * DK + c8);
        }
        const __half* vsrc = vg + (size_t)kt * 64 * DK;
        #pragma unroll
        for (int i = tid; i < 384; i += 256) {
            const int row = i / 6, c8 = (i % 6) * 8;
            cp_async16(vh_sb + (uint32_t)bufsel * VB_BYTES + (row * VHP + c8) * 2,
                       vsrc + row * DK + c8);
        }
    };

    stage_tile(0, 0);
    cp_commit();

    // ---- stage Q tile + write ones-columns into ALL V buffers (cols 48..55
    //      are never touched by cp.async -> persist across all tiles) ----
    {
        const uint4* qsrc = (const uint4*)(Q + head_off + (size_t)qt * 128 * DK);
        #pragma unroll
        for (int i = tid; i < 768; i += 256) {
            const int row = i / 6, c8 = (i % 6) * 8;
            *(uint4*)&Psh[row * PPH + c8] = qsrc[i];
        }
        if (tid < 64 * NBUF) {
            const int bsel = tid >> 6, row = tid & 63;
            uint4 ones = { 0x00003C00u, 0u, 0u, 0u };   // {1.0h, 0...}
            *(uint4*)&Vsh[bsel * (VB_BYTES / 2) + row * VHP + 48] = ones;
        }
    }
    __syncthreads();

    // ---- Q fragments -> registers via ldmatrix ----
    uint32_t qf[3][4];
    #pragma unroll
    for (int ks = 0; ks < 3; ks++)
        ldsm_x4(qf[ks][0], qf[ks][1], qf[ks][2], qf[ks][3], paddr + ks * 32);

    float ctxa[7][4];                  // [0..5]: dk cols; [6]: row-sum column
    #pragma unroll
    for (int nt = 0; nt < 7; nt++)
        #pragma unroll
        for (int i = 0; i < 4; i++) ctxa[nt][i] = 0.0f;
    float mrun0 = -INFINITY, mrun1 = -INFINITY;

    const int NT = S / 64;
    int buf = 0, nbuf = 1;
    for (int kt = 0; kt < NT; kt++) {
        if (kt + 1 < NT) {
            stage_tile(kt + 1, nbuf);
            cp_commit();
            cp_wait<1>();
        } else {
            cp_wait<0>();
        }
        __syncthreads();     // single barrier per tile (3-buffer ring)

        const uint32_t kbuf = kaddr + (uint32_t)buf * KB_BYTES;
        const uint32_t vbuf = vaddr + (uint32_t)buf * VB_BYTES;

        // ---- scores = Q @ K^T (fp16 mma, log2-domain) ----
        float sc[8][4];
        #pragma unroll
        for (int nt = 0; nt < 8; nt++)
            #pragma unroll
            for (int i = 0; i < 4; i++) sc[nt][i] = 0.0f;

        #pragma unroll
        for (int ks = 0; ks < 3; ks++) {
            const uint32_t ka = kbuf + ks * 32;
            #pragma unroll
            for (int p = 0; p < 4; p++) {
                uint32_t b0, b1, b2, b3;
                ldsm_x4(b0, b1, b2, b3, ka + p * (16 * KPH * 2));
                uint32_t f0[2] = { b0, b1 };
                uint32_t f1[2] = { b2, b3 };
                mma_f16(sc[2 * p],     qf[ks], f0);
                mma_f16(sc[2 * p + 1], qf[ks], f1);
            }
        }

        // ---- online max (register + shfl; rows warp-local) ----
        float m0 = sc[0][0], m1 = sc[0][2];
        #pragma unroll
        for (int nt = 0; nt < 8; nt++) {
            m0 = fmaxf(m0, fmaxf(sc[nt][0], sc[nt][1]));
            m1 = fmaxf(m1, fmaxf(sc[nt][2], sc[nt][3]));
        }
        m0 = fmaxf(m0, __shfl_xor_sync(0xFFFFFFFF, m0, 1));
        m0 = fmaxf(m0, __shfl_xor_sync(0xFFFFFFFF, m0, 2));
        m1 = fmaxf(m1, __shfl_xor_sync(0xFFFFFFFF, m1, 1));
        m1 = fmaxf(m1, __shfl_xor_sync(0xFFFFFFFF, m1, 2));

        const float mn0 = fmaxf(mrun0, m0);
        const float mn1 = fmaxf(mrun1, m1);
        const float corr0 = exp2f(mrun0 - mn0);   // exp2(-inf)=0 first time
        const float corr1 = exp2f(mrun1 - mn1);
        mrun0 = mn0; mrun1 = mn1;
        #pragma unroll
        for (int nt = 0; nt < 7; nt++) {
            ctxa[nt][0] *= corr0; ctxa[nt][1] *= corr0;
            ctxa[nt][2] *= corr1; ctxa[nt][3] *= corr1;
        }

        // ---- ctx (+rowsum col) += P @ V; P = ex2.f16x2(s - m) on the fly ----
        #pragma unroll
        for (int ck = 0; ck < 4; ck++) {
            uint32_t pa[4];
            pa[0] = h2exp2(packh2(sc[2*ck][0]   - mn0, sc[2*ck][1]   - mn0));
            pa[1] = h2exp2(packh2(sc[2*ck][2]   - mn1, sc[2*ck][3]   - mn1));
            pa[2] = h2exp2(packh2(sc[2*ck+1][0] - mn0, sc[2*ck+1][1] - mn0));
            pa[3] = h2exp2(packh2(sc[2*ck+1][2] - mn1, sc[2*ck+1][3] - mn1));
            const uint32_t vck = vbuf + ck * (16 * VHP * 2);
            #pragma unroll
            for (int t = 0; t < 3; t++) {
                uint32_t b0, b1, b2, b3;
                ldsm_x4_trans(b0, b1, b2, b3, vck + t * 32);
                uint32_t f0[2] = { b0, b1 };
                uint32_t f1[2] = { b2, b3 };
                mma_f16(ctxa[2 * t],     pa, f0);
                mma_f16(ctxa[2 * t + 1], pa, f1);
            }
            // 7th n-tile: cols 48-55 (col 48 = ones -> row sums)
            {
                uint32_t b0, b1, b2, b3;
                ldsm_x4_trans(b0, b1, b2, b3, vck + 3 * 32);
                uint32_t f0[2] = { b0, b1 };
                mma_f16(ctxa[6], pa, f0);
            }
        }

        buf = nbuf;
        nbuf = (nbuf == NBUF - 1) ? 0 : nbuf + 1;
    }

    // ---- epilogue: lrun = ctx col 48 (broadcast within 4-lane group) ----
    const float l0 = __shfl_sync(0xFFFFFFFF, ctxa[6][0], lane & 28);
    const float l1 = __shfl_sync(0xFFFFFFFF, ctxa[6][2], lane & 28);
    const float inv0 = 1.0f / l0;
    const float inv1 = 1.0f / l1;

    const int srow0 = qt * 128 + r0 + g;
    __half* out0 = ctx + ((size_t)b * S + srow0)     * DIM + h * DK;
    __half* out1 = ctx + ((size_t)b * S + srow0 + 8) * DIM + h * DK;
    #pragma unroll
    for (int nt = 0; nt < 6; nt++) {
        const int col = nt * 8 + 2 * tig;
        *(uint32_t*)(out0 + col) = packh2(ctxa[nt][0] * inv0, ctxa[nt][1] * inv0);
        *(uint32_t*)(out1 + col) = packh2(ctxa[nt][2] * inv1, ctxa[nt][3] * inv1);
    }
}

// ---------------------------------------------------------------------------
extern "C" void kernel_launch(void* const* d_in, const int* in_sizes, int n_in,
                              void* d_out, int out_size)
{
    const float* x  = (const float*)d_in[0];
    const float* Wq = (const float*)d_in[1];
    const float* bq = (const float*)d_in[2];
    const float* Wk = (const float*)d_in[3];
    const float* bk = (const float*)d_in[4];
    const float* Wv = (const float*)d_in[5];
    const float* bv = (const float*)d_in[6];
    const float* Wo = (const float*)d_in[7];
    const float* bo = (const float*)d_in[8];
    float* out = (float*)d_out;

    __half *q, *k, *v, *ctx, *cvt;
    cudaGetSymbolAddress((void**)&q,   g_q);
    cudaGetSymbolAddress((void**)&k,   g_k);
    cudaGetSymbolAddress((void**)&v,   g_v);
    cudaGetSymbolAddress((void**)&ctx, g_ctx);
    cudaGetSymbolAddress((void**)&cvt, g_cvt);

    const __half* xc  = cvt;
    const __half* Wqc = cvt + XC_ELEMS;
    const __half* Wkc = cvt + XC_ELEMS + WC_ELEMS;
    const __half* Wvc = cvt + XC_ELEMS + 2 * WC_ELEMS;
    const __half* Woc = cvt + XC_ELEMS + 3 * WC_ELEMS;

    cudaFuncSetAttribute(gemm_pipe_kernel<true>,
                         cudaFuncAttributeMaxDynamicSharedMemorySize, GEMM_SMEM_BYTES);
    cudaFuncSetAttribute(gemm_pipe_kernel<false>,
                         cudaFuncAttributeMaxDynamicSharedMemorySize, GEMM_SMEM_BYTES);
    cudaFuncSetAttribute(attention_mma_kernel,
                         cudaFuncAttributeMaxDynamicSharedMemorySize, ATT_SMEM_BYTES);

    // (1/sqrt(48)) * log2(e): scores emerge in log2 domain
    const float qscale = 0.14433756729740643f * 1.4426950408889634f;

    // Pre-convert x + all weights to fp16
    convert_f16_kernel<<<1184, 256>>>(x, Wq, Wk, Wv, Wo, (uint32_t*)cvt);

    // Fused Q/K/V projections: one launch, 36x32 = 1152 blocks
    dim3 qkv_grid(36, MROWS / 128);
    gemm_pipe_kernel<true><<<qkv_grid, 256, GEMM_SMEM_BYTES>>>(
        xc, Wqc, bq, q, Wkc, bk, k, Wvc, bv, v, MROWS, DIM, DIM, qscale);

    // Attention
    dim3 agrd(S / 128, HEADS, B);                // (16, 16, 2)
    attention_mma_kernel<<<agrd, 256, ATT_SMEM_BYTES>>>(q, k, v, ctx);

    // Output projection
    dim3 o_grid(DIM / 64, MROWS / 128);          // (12, 32)
    gemm_pipe_kernel<false><<<o_grid, 256, GEMM_SMEM_BYTES>>>(
        ctx, Woc, bo, out, nullptr, nullptr, nullptr,
        nullptr, nullptr, nullptr, MROWS, DIM, DIM, 1.0f);
}

// round 15
// speedup vs baseline: 1.1051x; 1.0236x over previous
#include <cuda_runtime.h>
#include <cuda_fp16.h>
#include <math.h>
#include <stdint.h>

#define DIM   768
#define HEADS 16
#define DK    48
#define B     2
#define S     2048
#define MROWS (B * S)          // 4096

// Scratch (static device globals — no runtime allocation)
__device__ __half g_q[B * HEADS * S * DK];    // fp16, pre-scaled (1/sqrt(dk))*log2(e)
__device__ __half g_k[B * HEADS * S * DK];    // fp16
__device__ __half g_v[B * HEADS * S * DK];    // fp16
__device__ __half g_ctx[MROWS * DIM];         // fp16 attention output

#define XC_ELEMS (MROWS * DIM)                // 3145728
#define WC_ELEMS (DIM * DIM)                  // 589824
__device__ __half g_cvt[XC_ELEMS + 4 * WC_ELEMS];  // fp16 x | Wq | Wk | Wv | Wo

// ---------------------------------------------------------------------------
// helpers
// ---------------------------------------------------------------------------
__device__ __forceinline__ uint32_t packh2(float lo, float hi) {
    __half2 h = __floats2half2_rn(lo, hi);
    return *reinterpret_cast<uint32_t*>(&h);
}

__device__ __forceinline__ uint32_t h2exp2(uint32_t x) {
    uint32_t r;
    asm("ex2.approx.f16x2 %0, %1;" : "=r"(r) : "r"(x));
    return r;
}

__device__ __forceinline__ void mma_f16(float c[4],
                                        const uint32_t a[4],
                                        const uint32_t b[2]) {
    asm volatile(
        "mma.sync.aligned.m16n8k16.row.col.f32.f16.f16.f32 "
        "{%0,%1,%2,%3}, {%4,%5,%6,%7}, {%8,%9}, {%0,%1,%2,%3};\n"
        : "+f"(c[0]), "+f"(c[1]), "+f"(c[2]), "+f"(c[3])
        : "r"(a[0]), "r"(a[1]), "r"(a[2]), "r"(a[3]),
          "r"(b[0]), "r"(b[1]));
}

__device__ __forceinline__ void ldsm_x4(uint32_t& r0, uint32_t& r1,
                                        uint32_t& r2, uint32_t& r3,
                                        uint32_t saddr) {
    asm volatile(
        "ldmatrix.sync.aligned.m8n8.x4.shared.b16 {%0,%1,%2,%3}, [%4];"
        : "=r"(r0), "=r"(r1), "=r"(r2), "=r"(r3) : "r"(saddr));
}

__device__ __forceinline__ void ldsm_x4_trans(uint32_t& r0, uint32_t& r1,
                                              uint32_t& r2, uint32_t& r3,
                                              uint32_t saddr) {
    asm volatile(
        "ldmatrix.sync.aligned.m8n8.x4.trans.shared.b16 {%0,%1,%2,%3}, [%4];"
        : "=r"(r0), "=r"(r1), "=r"(r2), "=r"(r3) : "r"(saddr));
}

__device__ __forceinline__ void cp_async16(uint32_t saddr, const void* gptr) {
    asm volatile("cp.async.cg.shared.global [%0], [%1], 16;"
                 :: "r"(saddr), "l"(gptr));
}
__device__ __forceinline__ void cp_commit() {
    asm volatile("cp.async.commit_group;");
}
template <int N>
__device__ __forceinline__ void cp_wait() {
    asm volatile("cp.async.wait_group %0;" :: "n"(N));
}

// ---------------------------------------------------------------------------
// Elementwise fp16 pre-conversion: x, Wq, Wk, Wv, Wo -> g_cvt
// ---------------------------------------------------------------------------
__global__ __launch_bounds__(256)
void convert_f16_kernel(const float* __restrict__ x,
                        const float* __restrict__ Wq,
                        const float* __restrict__ Wk,
                        const float* __restrict__ Wv,
                        const float* __restrict__ Wo,
                        uint32_t* __restrict__ out)
{
    const int total8 = (XC_ELEMS + 4 * WC_ELEMS) / 8;
    for (int i = blockIdx.x * blockDim.x + threadIdx.x; i < total8;
         i += gridDim.x * blockDim.x) {
        const int e = i * 8;
        const float* src;
        if (e < XC_ELEMS) {
            src = x + e;
        } else {
            const int r = e - XC_ELEMS;
            const int w = r / WC_ELEMS;
            const int off = r % WC_ELEMS;
            src = (w == 0 ? Wq : w == 1 ? Wk : w == 2 ? Wv : Wo) + off;
        }
        float4 v0 = *(const float4*)src;
        float4 v1 = *(const float4*)(src + 4);
        uint4 u;
        u.x = packh2(v0.x, v0.y);
        u.y = packh2(v0.z, v0.w);
        u.z = packh2(v1.x, v1.y);
        u.w = packh2(v1.z, v1.w);
        *(uint4*)(out + e / 2) = u;
    }
}

// ---------------------------------------------------------------------------
// Pipelined fp16 tensor-core GEMM (measured-best config, FROZEN):
// out = A[M,K] @ W[N,K]^T + bias[N], fp16 in, fp32 accum, mma.m16n8k16.
// Block tile 128x64, BK=32 halfs, 8 warps as 4x2. 4-stage cp.async ring,
// prefetch depth 2, one __syncthreads per slab. Pitch 40 halfs. 61440B smem
// -> 3 CTAs/SM.
// ---------------------------------------------------------------------------
#define BKH 32
#define APH 40
#define A_BYTES (128 * APH * 2)      // 10240
#define B_BYTES (64 * APH * 2)       // 5120
#define NSTAGE 4
#define GEMM_SMEM_BYTES (NSTAGE * (A_BYTES + B_BYTES))   // 61440

template <bool FUSED>
__global__ __launch_bounds__(256)
void gemm_pipe_kernel(const __half* __restrict__ A,
                      const __half* __restrict__ W0, const float* __restrict__ b0,
                      void* __restrict__ o0,
                      const __half* __restrict__ W1, const float* __restrict__ b1,
                      void* __restrict__ o1,
                      const __half* __restrict__ W2, const float* __restrict__ b2,
                      void* __restrict__ o2,
                      int M, int N, int K, float qscale)
{
    extern __shared__ uint32_t smem[];

    const int tid  = threadIdx.x;
    const int lane = tid & 31;
    const int warp = tid >> 5;
    const int warpM = warp >> 1;
    const int warpN = warp & 1;
    const int g   = lane >> 2;
    const int tig = lane & 3;
    const int mi  = lane >> 3;
    const int ri  = lane & 7;

    int seg = 0, bnx = blockIdx.x;
    const __half* W = W0; const float* bias = b0; void* out = o0;
    if (FUSED) {
        seg = blockIdx.x / 12;
        bnx = blockIdx.x % 12;
        if (seg == 1)      { W = W1; bias = b1; out = o1; }
        else if (seg == 2) { W = W2; bias = b2; out = o2; }
    }

    const int bm = blockIdx.y * 128;
    const int bn = bnx * 64;

    const int lrA = tid >> 1;
    const int lkA = (tid & 1) * 16;
    const int lrB = tid >> 2;
    const int lkB = (tid & 3) * 8;

    const __half* Aptr = A + (size_t)(bm + lrA) * K + lkA;
    const __half* Wptr = W + (size_t)(bn + lrB) * K + lkB;

    const int arow = warpM * 32;
    const int bcol = warpN * 32;

    const uint32_t as_sb = (uint32_t)__cvta_generic_to_shared(smem);
    const uint32_t bs_sb = as_sb + NSTAGE * A_BYTES;
    const uint32_t aaddr0 = as_sb +
        ((arow + (mi & 1) * 8 + ri) * APH + (mi >> 1) * 8) * 2;
    const uint32_t baddr0 = bs_sb +
        ((bcol + (mi >> 1) * 8 + ri) * APH + (mi & 1) * 8) * 2;

    auto stage = [&](int s, int buf) {
        const __half* ap = Aptr + s * BKH;
        #pragma unroll
        for (int i = 0; i < 2; i++)
            cp_async16(as_sb + (uint32_t)buf * A_BYTES +
                           (lrA * APH + lkA + i * 8) * 2,
                       ap + i * 8);
        const __half* wp = Wptr + s * BKH;
        cp_async16(bs_sb + (uint32_t)buf * B_BYTES + (lrB * APH + lkB) * 2, wp);
    };

    float c[2][4][4];
    #pragma unroll
    for (int mt = 0; mt < 2; mt++)
        #pragma unroll
        for (int nt = 0; nt < 4; nt++)
            #pragma unroll
            for (int i = 0; i < 4; i++) c[mt][nt][i] = 0.0f;

    const int NS = K / BKH;      // 24 slabs
    stage(0, 0); cp_commit();
    stage(1, 1); cp_commit();
    stage(2, 2); cp_commit();

    for (int s = 0; s < NS; s++) {
        if (s + 2 < NS)      cp_wait<2>();
        else if (s + 1 < NS) cp_wait<1>();
        else                 cp_wait<0>();
        __syncthreads();
        if (s + 3 < NS) { stage(s + 3, (s + 3) & 3); cp_commit(); }

        const int buf = s & 3;
        const uint32_t abuf = aaddr0 + (uint32_t)buf * A_BYTES;
        const uint32_t bbuf = baddr0 + (uint32_t)buf * B_BYTES;
        #pragma unroll
        for (int ks = 0; ks < 2; ks++) {
            const uint32_t koff = ks * 32;
            uint32_t afr[2][4], bfr[4][2];
            #pragma unroll
            for (int mt = 0; mt < 2; mt++)
                ldsm_x4(afr[mt][0], afr[mt][1], afr[mt][2], afr[mt][3],
                        abuf + mt * (16 * APH * 2) + koff);
            #pragma unroll
            for (int p = 0; p < 2; p++)
                ldsm_x4(bfr[2*p][0], bfr[2*p][1], bfr[2*p+1][0], bfr[2*p+1][1],
                        bbuf + p * (16 * APH * 2) + koff);
            #pragma unroll
            for (int mt = 0; mt < 2; mt++)
                #pragma unroll
                for (int nt = 0; nt < 4; nt++)
                    mma_f16(c[mt][nt], afr[mt], bfr[nt]);
        }
    }

    // ---- epilogue ----
    #pragma unroll
    for (int mt = 0; mt < 2; mt++) {
        #pragma unroll
        for (int nt = 0; nt < 4; nt++) {
            #pragma unroll
            for (int i = 0; i < 4; i++) {
                const int m = bm + arow + mt * 16 + g + (i >> 1) * 8;
                const int n = bn + bcol + nt * 8 + 2 * tig + (i & 1);
                const float v = c[mt][nt][i] + bias[n];
                if (!FUSED) {
                    ((float*)out)[(size_t)m * N + n] = v;
                } else {
                    const int bidx = m / S;
                    const int s_   = m % S;
                    const int h    = n / DK;
                    const int d    = n % DK;
                    const size_t idx = (((size_t)bidx * HEADS + h) * S + s_) * DK + d;
                    const float sv = (seg == 0) ? v * qscale : v;
                    ((__half*)out)[idx] = __float2half_rn(sv);
                }
            }
        }
    }
}

// ---------------------------------------------------------------------------
// fp16 tensor-core flash attention, softmax-lite, 128-key staging tiles:
//   - K/V staged 128 keys at a time (16 staging barriers instead of 32);
//     compute proceeds in two 64-key chunks (score regs / softmax unchanged)
//   - 3-buffer ring, single __syncthreads per staging tile
//   - Q pre-scaled by (1/sqrt(dk))*log2(e) -> scores in log2 domain
//   - P = ex2.approx.f16x2 of packed (s - m), directly in mma A form
//   - ones-column trick: V smem col 48 = 1.0 -> 7th PV n-tile accumulates
//     row sums inside the mma (no lrun FADDs, no epilogue reductions)
// ---------------------------------------------------------------------------
#define KPH 56
#define PPH 56
#define VHP 56
#define TKEYS 128                        // keys per staging tile
#define KB_BYTES (TKEYS * KPH * 2)       // 14336
#define VB_BYTES (TKEYS * VHP * 2)       // 14336
#define PS_BYTES (128 * PPH * 2)         // 14336
#define NBUF 3
#define CHUNK_BYTES (64 * KPH * 2)       // 7168 (64-key compute chunk)
#define ATT_SMEM_BYTES (NBUF * (KB_BYTES + VB_BYTES) + PS_BYTES)   // 100352

__global__ __launch_bounds__(256)
void attention_mma_kernel(const __half* __restrict__ Q,
                          const __half* __restrict__ K,
                          const __half* __restrict__ Vf,
                          __half* __restrict__ ctx)
{
    extern __shared__ uint32_t sm[];

    const int qt   = blockIdx.x;
    const int h    = blockIdx.y;
    const int b    = blockIdx.z;
    const int tid  = threadIdx.x;
    const int lane = tid & 31;
    const int warp = tid >> 5;
    const int g    = lane >> 2;
    const int tig  = lane & 3;
    const int mi   = lane >> 3;
    const int ri   = lane & 7;
    const int r0   = warp * 16;

    const size_t head_off = ((size_t)b * HEADS + h) * S * DK;

    const uint32_t base_sb = (uint32_t)__cvta_generic_to_shared(sm);
    const uint32_t ks_sb = base_sb;
    const uint32_t vh_sb = base_sb + NBUF * KB_BYTES;
    const uint32_t ps_sb = base_sb + NBUF * (KB_BYTES + VB_BYTES);
    __half* Vsh = (__half*)((char*)sm + NBUF * KB_BYTES);
    __half* Psh = (__half*)((char*)sm + NBUF * (KB_BYTES + VB_BYTES));

    const uint32_t kaddr = ks_sb + (((mi >> 1) * 8 + ri) * KPH + (mi & 1) * 8) * 2;
    const uint32_t paddr = ps_sb + ((r0 + (mi & 1) * 8 + ri) * PPH + (mi >> 1) * 8) * 2;
    const uint32_t vaddr = vh_sb + (((mi & 1) * 8 + ri) * VHP + (mi >> 1) * 8) * 2;

    const __half* kg = K + head_off;
    const __half* vg = Vf + head_off;

    // stage one 128-key tile (K + V), 6 cp.async per thread
    auto stage_tile = [&](int kt, int bufsel) {
        const __half* ksrc = kg + (size_t)kt * TKEYS * DK;
        #pragma unroll
        for (int i = tid; i < TKEYS * 6; i += 256) {
            const int row = i / 6, c8 = (i % 6) * 8;
            cp_async16(ks_sb + (uint32_t)bufsel * KB_BYTES + (row * KPH + c8) * 2,
                       ksrc + row * DK + c8);
        }
        const __half* vsrc = vg + (size_t)kt * TKEYS * DK;
        #pragma unroll
        for (int i = tid; i < TKEYS * 6; i += 256) {
            const int row = i / 6, c8 = (i % 6) * 8;
            cp_async16(vh_sb + (uint32_t)bufsel * VB_BYTES + (row * VHP + c8) * 2,
                       vsrc + row * DK + c8);
        }
    };

    stage_tile(0, 0);
    cp_commit();

    // ---- stage Q tile + write ones-columns into ALL V buffers (cols 48..55
    //      are never touched by cp.async -> persist across all tiles) ----
    {
        const uint4* qsrc = (const uint4*)(Q + head_off + (size_t)qt * 128 * DK);
        #pragma unroll
        for (int i = tid; i < 768; i += 256) {
            const int row = i / 6, c8 = (i % 6) * 8;
            *(uint4*)&Psh[row * PPH + c8] = qsrc[i];
        }
        for (int i = tid; i < TKEYS * NBUF; i += 256) {
            const int bsel = i / TKEYS, row = i % TKEYS;
            uint4 ones = { 0x00003C00u, 0u, 0u, 0u };   // {1.0h, 0...}
            *(uint4*)&Vsh[bsel * (VB_BYTES / 2) + row * VHP + 48] = ones;
        }
    }
    __syncthreads();

    // ---- Q fragments -> registers via ldmatrix ----
    uint32_t qf[3][4];
    #pragma unroll
    for (int ks = 0; ks < 3; ks++)
        ldsm_x4(qf[ks][0], qf[ks][1], qf[ks][2], qf[ks][3], paddr + ks * 32);

    float ctxa[7][4];                  // [0..5]: dk cols; [6]: row-sum column
    #pragma unroll
    for (int nt = 0; nt < 7; nt++)
        #pragma unroll
        for (int i = 0; i < 4; i++) ctxa[nt][i] = 0.0f;
    float mrun0 = -INFINITY, mrun1 = -INFINITY;

    const int NT = S / TKEYS;          // 16 staging tiles
    int buf = 0, nbuf = 1;
    for (int kt = 0; kt < NT; kt++) {
        if (kt + 1 < NT) {
            stage_tile(kt + 1, nbuf);
            cp_commit();
            cp_wait<1>();
        } else {
            cp_wait<0>();
        }
        __syncthreads();     // single barrier per 128-key tile

        // ---- two 64-key compute chunks ----
        #pragma unroll
        for (int ch = 0; ch < 2; ch++) {
            const uint32_t kbuf = kaddr + (uint32_t)buf * KB_BYTES + ch * CHUNK_BYTES;
            const uint32_t vbuf = vaddr + (uint32_t)buf * VB_BYTES + ch * CHUNK_BYTES;

            // scores = Q @ K^T (fp16 mma, log2-domain)
            float sc[8][4];
            #pragma unroll
            for (int nt = 0; nt < 8; nt++)
                #pragma unroll
                for (int i = 0; i < 4; i++) sc[nt][i] = 0.0f;

            #pragma unroll
            for (int ks = 0; ks < 3; ks++) {
                const uint32_t ka = kbuf + ks * 32;
                #pragma unroll
                for (int p = 0; p < 4; p++) {
                    uint32_t b0, b1, b2, b3;
                    ldsm_x4(b0, b1, b2, b3, ka + p * (16 * KPH * 2));
                    uint32_t f0[2] = { b0, b1 };
                    uint32_t f1[2] = { b2, b3 };
                    mma_f16(sc[2 * p],     qf[ks], f0);
                    mma_f16(sc[2 * p + 1], qf[ks], f1);
                }
            }

            // online max (register + shfl; rows warp-local)
            float m0 = sc[0][0], m1 = sc[0][2];
            #pragma unroll
            for (int nt = 0; nt < 8; nt++) {
                m0 = fmaxf(m0, fmaxf(sc[nt][0], sc[nt][1]));
                m1 = fmaxf(m1, fmaxf(sc[nt][2], sc[nt][3]));
            }
            m0 = fmaxf(m0, __shfl_xor_sync(0xFFFFFFFF, m0, 1));
            m0 = fmaxf(m0, __shfl_xor_sync(0xFFFFFFFF, m0, 2));
            m1 = fmaxf(m1, __shfl_xor_sync(0xFFFFFFFF, m1, 1));
            m1 = fmaxf(m1, __shfl_xor_sync(0xFFFFFFFF, m1, 2));

            const float mn0 = fmaxf(mrun0, m0);
            const float mn1 = fmaxf(mrun1, m1);
            const float corr0 = exp2f(mrun0 - mn0);   // exp2(-inf)=0 first time
            const float corr1 = exp2f(mrun1 - mn1);
            mrun0 = mn0; mrun1 = mn1;
            #pragma unroll
            for (int nt = 0; nt < 7; nt++) {
                ctxa[nt][0] *= corr0; ctxa[nt][1] *= corr0;
                ctxa[nt][2] *= corr1; ctxa[nt][3] *= corr1;
            }

            // ctx (+rowsum col) += P @ V; P = ex2.f16x2(s - m) on the fly
            #pragma unroll
            for (int ck = 0; ck < 4; ck++) {
                uint32_t pa[4];
                pa[0] = h2exp2(packh2(sc[2*ck][0]   - mn0, sc[2*ck][1]   - mn0));
                pa[1] = h2exp2(packh2(sc[2*ck][2]   - mn1, sc[2*ck][3]   - mn1));
                pa[2] = h2exp2(packh2(sc[2*ck+1][0] - mn0, sc[2*ck+1][1] - mn0));
                pa[3] = h2exp2(packh2(sc[2*ck+1][2] - mn1, sc[2*ck+1][3] - mn1));
                const uint32_t vck = vbuf + ck * (16 * VHP * 2);
                #pragma unroll
                for (int t = 0; t < 3; t++) {
                    uint32_t b0, b1, b2, b3;
                    ldsm_x4_trans(b0, b1, b2, b3, vck + t * 32);
                    uint32_t f0[2] = { b0, b1 };
                    uint32_t f1[2] = { b2, b3 };
                    mma_f16(ctxa[2 * t],     pa, f0);
                    mma_f16(ctxa[2 * t + 1], pa, f1);
                }
                // 7th n-tile: cols 48-55 (col 48 = ones -> row sums)
                {
                    uint32_t b0, b1, b2, b3;
                    ldsm_x4_trans(b0, b1, b2, b3, vck + 3 * 32);
                    uint32_t f0[2] = { b0, b1 };
                    mma_f16(ctxa[6], pa, f0);
                }
            }
        }

        buf = nbuf;
        nbuf = (nbuf == NBUF - 1) ? 0 : nbuf + 1;
    }

    // ---- epilogue: lrun = ctx col 48 (broadcast within 4-lane group) ----
    const float l0 = __shfl_sync(0xFFFFFFFF, ctxa[6][0], lane & 28);
    const float l1 = __shfl_sync(0xFFFFFFFF, ctxa[6][2], lane & 28);
    const float inv0 = 1.0f / l0;
    const float inv1 = 1.0f / l1;

    const int srow0 = qt * 128 + r0 + g;
    __half* out0 = ctx + ((size_t)b * S + srow0)     * DIM + h * DK;
    __half* out1 = ctx + ((size_t)b * S + srow0 + 8) * DIM + h * DK;
    #pragma unroll
    for (int nt = 0; nt < 6; nt++) {
        const int col = nt * 8 + 2 * tig;
        *(uint32_t*)(out0 + col) = packh2(ctxa[nt][0] * inv0, ctxa[nt][1] * inv0);
        *(uint32_t*)(out1 + col) = packh2(ctxa[nt][2] * inv1, ctxa[nt][3] * inv1);
    }
}

// ---------------------------------------------------------------------------
extern "C" void kernel_launch(void* const* d_in, const int* in_sizes, int n_in,
                              void* d_out, int out_size)
{
    const float* x  = (const float*)d_in[0];
    const float* Wq = (const float*)d_in[1];
    const float* bq = (const float*)d_in[2];
    const float* Wk = (const float*)d_in[3];
    const float* bk = (const float*)d_in[4];
    const float* Wv = (const float*)d_in[5];
    const float* bv = (const float*)d_in[6];
    const float* Wo = (const float*)d_in[7];
    const float* bo = (const float*)d_in[8];
    float* out = (float*)d_out;

    __half *q, *k, *v, *ctx, *cvt;
    cudaGetSymbolAddress((void**)&q,   g_q);
    cudaGetSymbolAddress((void**)&k,   g_k);
    cudaGetSymbolAddress((void**)&v,   g_v);
    cudaGetSymbolAddress((void**)&ctx, g_ctx);
    cudaGetSymbolAddress((void**)&cvt, g_cvt);

    const __half* xc  = cvt;
    const __half* Wqc = cvt + XC_ELEMS;
    const __half* Wkc = cvt + XC_ELEMS + WC_ELEMS;
    const __half* Wvc = cvt + XC_ELEMS + 2 * WC_ELEMS;
    const __half* Woc = cvt + XC_ELEMS + 3 * WC_ELEMS;

    cudaFuncSetAttribute(gemm_pipe_kernel<true>,
                         cudaFuncAttributeMaxDynamicSharedMemorySize, GEMM_SMEM_BYTES);
    cudaFuncSetAttribute(gemm_pipe_kernel<false>,
                         cudaFuncAttributeMaxDynamicSharedMemorySize, GEMM_SMEM_BYTES);
    cudaFuncSetAttribute(attention_mma_kernel,
                         cudaFuncAttributeMaxDynamicSharedMemorySize, ATT_SMEM_BYTES);

    // (1/sqrt(48)) * log2(e): scores emerge in log2 domain
    const float qscale = 0.14433756729740643f * 1.4426950408889634f;

    // Pre-convert x + all weights to fp16
    convert_f16_kernel<<<1184, 256>>>(x, Wq, Wk, Wv, Wo, (uint32_t*)cvt);

    // Fused Q/K/V projections: one launch, 36x32 = 1152 blocks
    dim3 qkv_grid(36, MROWS / 128);
    gemm_pipe_kernel<true><<<qkv_grid, 256, GEMM_SMEM_BYTES>>>(
        xc, Wqc, bq, q, Wkc, bk, k, Wvc, bv, v, MROWS, DIM, DIM, qscale);

    // Attention
    dim3 agrd(S / 128, HEADS, B);                // (16, 16, 2)
    attention_mma_kernel<<<agrd, 256, ATT_SMEM_BYTES>>>(q, k, v, ctx);

    // Output projection
    dim3 o_grid(DIM / 64, MROWS / 128);          // (12, 32)
    gemm_pipe_kernel<false><<<o_grid, 256, GEMM_SMEM_BYTES>>>(
        ctx, Woc, bo, out, nullptr, nullptr, nullptr,
        nullptr, nullptr, nullptr, MROWS, DIM, DIM, 1.0f);
}

// round 16
// speedup vs baseline: 1.1409x; 1.0324x over previous
#include <cuda_runtime.h>
#include <cuda_fp16.h>
#include <math.h>
#include <stdint.h>

#define DIM   768
#define HEADS 16
#define DK    48
#define B     2
#define S     2048
#define MROWS (B * S)          // 4096

// Scratch (static device globals — no runtime allocation)
__device__ __half g_q[B * HEADS * S * DK];    // fp16, pre-scaled (1/sqrt(dk))*log2(e)
__device__ __half g_k[B * HEADS * S * DK];    // fp16
__device__ __half g_v[B * HEADS * S * DK];    // fp16
__device__ __half g_ctx[MROWS * DIM];         // fp16 attention output

#define XC_ELEMS (MROWS * DIM)                // 3145728
#define WC_ELEMS (DIM * DIM)                  // 589824
__device__ __half g_cvt[XC_ELEMS + 4 * WC_ELEMS];  // fp16 x | Wq | Wk | Wv | Wo

// ---------------------------------------------------------------------------
// helpers
// ---------------------------------------------------------------------------
__device__ __forceinline__ uint32_t packh2(float lo, float hi) {
    __half2 h = __floats2half2_rn(lo, hi);
    return *reinterpret_cast<uint32_t*>(&h);
}

__device__ __forceinline__ uint32_t h2exp2(uint32_t x) {
    uint32_t r;
    asm("ex2.approx.f16x2 %0, %1;" : "=r"(r) : "r"(x));
    return r;
}

__device__ __forceinline__ void mma_f16(float c[4],
                                        const uint32_t a[4],
                                        const uint32_t b[2]) {
    asm volatile(
        "mma.sync.aligned.m16n8k16.row.col.f32.f16.f16.f32 "
        "{%0,%1,%2,%3}, {%4,%5,%6,%7}, {%8,%9}, {%0,%1,%2,%3};\n"
        : "+f"(c[0]), "+f"(c[1]), "+f"(c[2]), "+f"(c[3])
        : "r"(a[0]), "r"(a[1]), "r"(a[2]), "r"(a[3]),
          "r"(b[0]), "r"(b[1]));
}

__device__ __forceinline__ void ldsm_x4(uint32_t& r0, uint32_t& r1,
                                        uint32_t& r2, uint32_t& r3,
                                        uint32_t saddr) {
    asm volatile(
        "ldmatrix.sync.aligned.m8n8.x4.shared.b16 {%0,%1,%2,%3}, [%4];"
        : "=r"(r0), "=r"(r1), "=r"(r2), "=r"(r3) : "r"(saddr));
}

__device__ __forceinline__ void ldsm_x4_trans(uint32_t& r0, uint32_t& r1,
                                              uint32_t& r2, uint32_t& r3,
                                              uint32_t saddr) {
    asm volatile(
        "ldmatrix.sync.aligned.m8n8.x4.trans.shared.b16 {%0,%1,%2,%3}, [%4];"
        : "=r"(r0), "=r"(r1), "=r"(r2), "=r"(r3) : "r"(saddr));
}

__device__ __forceinline__ void cp_async16(uint32_t saddr, const void* gptr) {
    asm volatile("cp.async.cg.shared.global [%0], [%1], 16;"
                 :: "r"(saddr), "l"(gptr));
}
__device__ __forceinline__ void cp_commit() {
    asm volatile("cp.async.commit_group;");
}
template <int N>
__device__ __forceinline__ void cp_wait() {
    asm volatile("cp.async.wait_group %0;" :: "n"(N));
}

// ---------------------------------------------------------------------------
// Elementwise fp16 pre-conversion: x, Wq, Wk, Wv, Wo -> g_cvt
// ---------------------------------------------------------------------------
__global__ __launch_bounds__(256)
void convert_f16_kernel(const float* __restrict__ x,
                        const float* __restrict__ Wq,
                        const float* __restrict__ Wk,
                        const float* __restrict__ Wv,
                        const float* __restrict__ Wo,
                        uint32_t* __restrict__ out)
{
    const int total8 = (XC_ELEMS + 4 * WC_ELEMS) / 8;
    for (int i = blockIdx.x * blockDim.x + threadIdx.x; i < total8;
         i += gridDim.x * blockDim.x) {
        const int e = i * 8;
        const float* src;
        if (e < XC_ELEMS) {
            src = x + e;
        } else {
            const int r = e - XC_ELEMS;
            const int w = r / WC_ELEMS;
            const int off = r % WC_ELEMS;
            src = (w == 0 ? Wq : w == 1 ? Wk : w == 2 ? Wv : Wo) + off;
        }
        float4 v0 = *(const float4*)src;
        float4 v1 = *(const float4*)(src + 4);
        uint4 u;
        u.x = packh2(v0.x, v0.y);
        u.y = packh2(v0.z, v0.w);
        u.z = packh2(v1.x, v1.y);
        u.w = packh2(v1.z, v1.w);
        *(uint4*)(out + e / 2) = u;
    }
}

// ---------------------------------------------------------------------------
// Pipelined fp16 tensor-core GEMM: out = A[M,K] @ W[N,K]^T + bias[N]
// Block tile 128x128, BK=32 halfs, 8 warps as 4x2 (warp tile 32x64).
// Per ks-step: 6 LDSM.x4 feed 16 mma (twice the work per barrier interval
// of the old 128x64 tile). 4-stage cp.async ring, prefetch depth 2, one
// __syncthreads per slab. Pitch 40 halfs. 81920B smem, <=128 regs -> 2 CTAs/SM.
// FUSED=true : blockIdx.x/6 -> segment 0:q(*qscale) 1:k 2:v, fp16 scatter.
// FUSED=false: plain fp32 out [M,N].
// ---------------------------------------------------------------------------
#define BKH 32
#define APH 40
#define A_BYTES (128 * APH * 2)      // 10240
#define B_BYTES (128 * APH * 2)      // 10240
#define NSTAGE 4
#define GEMM_SMEM_BYTES (NSTAGE * (A_BYTES + B_BYTES))   // 81920

template <bool FUSED>
__global__ __launch_bounds__(256, 2)
void gemm_pipe_kernel(const __half* __restrict__ A,
                      const __half* __restrict__ W0, const float* __restrict__ b0,
                      void* __restrict__ o0,
                      const __half* __restrict__ W1, const float* __restrict__ b1,
                      void* __restrict__ o1,
                      const __half* __restrict__ W2, const float* __restrict__ b2,
                      void* __restrict__ o2,
                      int M, int N, int K, float qscale)
{
    extern __shared__ uint32_t smem[];

    const int tid  = threadIdx.x;
    const int lane = tid & 31;
    const int warp = tid >> 5;
    const int warpM = warp >> 1;             // 0..3
    const int warpN = warp & 1;              // 0..1
    const int g   = lane >> 2;
    const int tig = lane & 3;
    const int mi  = lane >> 3;
    const int ri  = lane & 7;

    int seg = 0, bnx = blockIdx.x;
    const __half* W = W0; const float* bias = b0; void* out = o0;
    if (FUSED) {
        seg = blockIdx.x / 6;
        bnx = blockIdx.x % 6;
        if (seg == 1)      { W = W1; bias = b1; out = o1; }
        else if (seg == 2) { W = W2; bias = b2; out = o2; }
    }

    const int bm = blockIdx.y * 128;
    const int bn = bnx * 128;

    const int lrA = tid >> 1;                // 0..127
    const int lkA = (tid & 1) * 16;          // 0 / 16 (halfs)

    const __half* Aptr = A + (size_t)(bm + lrA) * K + lkA;
    const __half* Wptr = W + (size_t)(bn + lrA) * K + lkA;

    const int arow = warpM * 32;
    const int bcol = warpN * 64;

    const uint32_t as_sb = (uint32_t)__cvta_generic_to_shared(smem);
    const uint32_t bs_sb = as_sb + NSTAGE * A_BYTES;
    // A frag: row = arow + mt*16 + (mi&1)*8 + ri, kcol = ks*16 + (mi>>1)*8
    const uint32_t aaddr0 = as_sb +
        ((arow + (mi & 1) * 8 + ri) * APH + (mi >> 1) * 8) * 2;
    // B frag: nrow = bcol + p*16 + (mi>>1)*8 + ri, kcol = ks*16 + (mi&1)*8
    const uint32_t baddr0 = bs_sb +
        ((bcol + (mi >> 1) * 8 + ri) * APH + (mi & 1) * 8) * 2;

    auto stage = [&](int s, int buf) {
        const __half* ap = Aptr + s * BKH;
        #pragma unroll
        for (int i = 0; i < 2; i++)
            cp_async16(as_sb + (uint32_t)buf * A_BYTES +
                           (lrA * APH + lkA + i * 8) * 2,
                       ap + i * 8);
        const __half* wp = Wptr + s * BKH;
        #pragma unroll
        for (int i = 0; i < 2; i++)
            cp_async16(bs_sb + (uint32_t)buf * B_BYTES +
                           (lrA * APH + lkA + i * 8) * 2,
                       wp + i * 8);
    };

    float c[2][8][4];
    #pragma unroll
    for (int mt = 0; mt < 2; mt++)
        #pragma unroll
        for (int nt = 0; nt < 8; nt++)
            #pragma unroll
            for (int i = 0; i < 4; i++) c[mt][nt][i] = 0.0f;

    const int NS = K / BKH;      // 24 slabs
    stage(0, 0); cp_commit();
    stage(1, 1); cp_commit();
    stage(2, 2); cp_commit();

    for (int s = 0; s < NS; s++) {
        if (s + 2 < NS)      cp_wait<2>();
        else if (s + 1 < NS) cp_wait<1>();
        else                 cp_wait<0>();
        __syncthreads();
        if (s + 3 < NS) { stage(s + 3, (s + 3) & 3); cp_commit(); }

        const int buf = s & 3;
        const uint32_t abuf = aaddr0 + (uint32_t)buf * A_BYTES;
        const uint32_t bbuf = baddr0 + (uint32_t)buf * B_BYTES;
        #pragma unroll
        for (int ks = 0; ks < 2; ks++) {
            const uint32_t koff = ks * 32;           // 16 halfs
            uint32_t afr[2][4], bfr[8][2];
            #pragma unroll
            for (int mt = 0; mt < 2; mt++)
                ldsm_x4(afr[mt][0], afr[mt][1], afr[mt][2], afr[mt][3],
                        abuf + mt * (16 * APH * 2) + koff);
            #pragma unroll
            for (int p = 0; p < 4; p++)
                ldsm_x4(bfr[2*p][0], bfr[2*p][1], bfr[2*p+1][0], bfr[2*p+1][1],
                        bbuf + p * (16 * APH * 2) + koff);
            #pragma unroll
            for (int mt = 0; mt < 2; mt++)
                #pragma unroll
                for (int nt = 0; nt < 8; nt++)
                    mma_f16(c[mt][nt], afr[mt], bfr[nt]);
        }
    }

    // ---- epilogue ----
    #pragma unroll
    for (int mt = 0; mt < 2; mt++) {
        #pragma unroll
        for (int nt = 0; nt < 8; nt++) {
            #pragma unroll
            for (int i = 0; i < 4; i++) {
                const int m = bm + arow + mt * 16 + g + (i >> 1) * 8;
                const int n = bn + bcol + nt * 8 + 2 * tig + (i & 1);
                const float v = c[mt][nt][i] + bias[n];
                if (!FUSED) {
                    ((float*)out)[(size_t)m * N + n] = v;
                } else {
                    const int bidx = m / S;
                    const int s_   = m % S;
                    const int h    = n / DK;
                    const int d    = n % DK;
                    const size_t idx = (((size_t)bidx * HEADS + h) * S + s_) * DK + d;
                    const float sv = (seg == 0) ? v * qscale : v;
                    ((__half*)out)[idx] = __float2half_rn(sv);
                }
            }
        }
    }
}

// ---------------------------------------------------------------------------
// fp16 tensor-core flash attention (round-15 version, FROZEN):
// softmax-lite, 128-key staging tiles, 3-buffer ring, single barrier/tile,
// log2-domain scores + ex2.approx.f16x2, ones-column row sums in the mma.
// ---------------------------------------------------------------------------
#define KPH 56
#define PPH 56
#define VHP 56
#define TKEYS 128
#define KB_BYTES (TKEYS * KPH * 2)       // 14336
#define VB_BYTES (TKEYS * VHP * 2)       // 14336
#define PS_BYTES (128 * PPH * 2)         // 14336
#define NBUF 3
#define CHUNK_BYTES (64 * KPH * 2)       // 7168
#define ATT_SMEM_BYTES (NBUF * (KB_BYTES + VB_BYTES) + PS_BYTES)   // 100352

__global__ __launch_bounds__(256)
void attention_mma_kernel(const __half* __restrict__ Q,
                          const __half* __restrict__ K,
                          const __half* __restrict__ Vf,
                          __half* __restrict__ ctx)
{
    extern __shared__ uint32_t sm[];

    const int qt   = blockIdx.x;
    const int h    = blockIdx.y;
    const int b    = blockIdx.z;
    const int tid  = threadIdx.x;
    const int lane = tid & 31;
    const int warp = tid >> 5;
    const int g    = lane >> 2;
    const int tig  = lane & 3;
    const int mi   = lane >> 3;
    const int ri   = lane & 7;
    const int r0   = warp * 16;

    const size_t head_off = ((size_t)b * HEADS + h) * S * DK;

    const uint32_t base_sb = (uint32_t)__cvta_generic_to_shared(sm);
    const uint32_t ks_sb = base_sb;
    const uint32_t vh_sb = base_sb + NBUF * KB_BYTES;
    const uint32_t ps_sb = base_sb + NBUF * (KB_BYTES + VB_BYTES);
    __half* Vsh = (__half*)((char*)sm + NBUF * KB_BYTES);
    __half* Psh = (__half*)((char*)sm + NBUF * (KB_BYTES + VB_BYTES));

    const uint32_t kaddr = ks_sb + (((mi >> 1) * 8 + ri) * KPH + (mi & 1) * 8) * 2;
    const uint32_t paddr = ps_sb + ((r0 + (mi & 1) * 8 + ri) * PPH + (mi >> 1) * 8) * 2;
    const uint32_t vaddr = vh_sb + (((mi & 1) * 8 + ri) * VHP + (mi >> 1) * 8) * 2;

    const __half* kg = K + head_off;
    const __half* vg = Vf + head_off;

    auto stage_tile = [&](int kt, int bufsel) {
        const __half* ksrc = kg + (size_t)kt * TKEYS * DK;
        #pragma unroll
        for (int i = tid; i < TKEYS * 6; i += 256) {
            const int row = i / 6, c8 = (i % 6) * 8;
            cp_async16(ks_sb + (uint32_t)bufsel * KB_BYTES + (row * KPH + c8) * 2,
                       ksrc + row * DK + c8);
        }
        const __half* vsrc = vg + (size_t)kt * TKEYS * DK;
        #pragma unroll
        for (int i = tid; i < TKEYS * 6; i += 256) {
            const int row = i / 6, c8 = (i % 6) * 8;
            cp_async16(vh_sb + (uint32_t)bufsel * VB_BYTES + (row * VHP + c8) * 2,
                       vsrc + row * DK + c8);
        }
    };

    stage_tile(0, 0);
    cp_commit();

    {
        const uint4* qsrc = (const uint4*)(Q + head_off + (size_t)qt * 128 * DK);
        #pragma unroll
        for (int i = tid; i < 768; i += 256) {
            const int row = i / 6, c8 = (i % 6) * 8;
            *(uint4*)&Psh[row * PPH + c8] = qsrc[i];
        }
        for (int i = tid; i < TKEYS * NBUF; i += 256) {
            const int bsel = i / TKEYS, row = i % TKEYS;
            uint4 ones = { 0x00003C00u, 0u, 0u, 0u };   // {1.0h, 0...}
            *(uint4*)&Vsh[bsel * (VB_BYTES / 2) + row * VHP + 48] = ones;
        }
    }
    __syncthreads();

    uint32_t qf[3][4];
    #pragma unroll
    for (int ks = 0; ks < 3; ks++)
        ldsm_x4(qf[ks][0], qf[ks][1], qf[ks][2], qf[ks][3], paddr + ks * 32);

    float ctxa[7][4];
    #pragma unroll
    for (int nt = 0; nt < 7; nt++)
        #pragma unroll
        for (int i = 0; i < 4; i++) ctxa[nt][i] = 0.0f;
    float mrun0 = -INFINITY, mrun1 = -INFINITY;

    const int NT = S / TKEYS;
    int buf = 0, nbuf = 1;
    for (int kt = 0; kt < NT; kt++) {
        if (kt + 1 < NT) {
            stage_tile(kt + 1, nbuf);
            cp_commit();
            cp_wait<1>();
        } else {
            cp_wait<0>();
        }
        __syncthreads();

        #pragma unroll
        for (int ch = 0; ch < 2; ch++) {
            const uint32_t kbuf = kaddr + (uint32_t)buf * KB_BYTES + ch * CHUNK_BYTES;
            const uint32_t vbuf = vaddr + (uint32_t)buf * VB_BYTES + ch * CHUNK_BYTES;

            float sc[8][4];
            #pragma unroll
            for (int nt = 0; nt < 8; nt++)
                #pragma unroll
                for (int i = 0; i < 4; i++) sc[nt][i] = 0.0f;

            #pragma unroll
            for (int ks = 0; ks < 3; ks++) {
                const uint32_t ka = kbuf + ks * 32;
                #pragma unroll
                for (int p = 0; p < 4; p++) {
                    uint32_t b0, b1, b2, b3;
                    ldsm_x4(b0, b1, b2, b3, ka + p * (16 * KPH * 2));
                    uint32_t f0[2] = { b0, b1 };
                    uint32_t f1[2] = { b2, b3 };
                    mma_f16(sc[2 * p],     qf[ks], f0);
                    mma_f16(sc[2 * p + 1], qf[ks], f1);
                }
            }

            float m0 = sc[0][0], m1 = sc[0][2];
            #pragma unroll
            for (int nt = 0; nt < 8; nt++) {
                m0 = fmaxf(m0, fmaxf(sc[nt][0], sc[nt][1]));
                m1 = fmaxf(m1, fmaxf(sc[nt][2], sc[nt][3]));
            }
            m0 = fmaxf(m0, __shfl_xor_sync(0xFFFFFFFF, m0, 1));
            m0 = fmaxf(m0, __shfl_xor_sync(0xFFFFFFFF, m0, 2));
            m1 = fmaxf(m1, __shfl_xor_sync(0xFFFFFFFF, m1, 1));
            m1 = fmaxf(m1, __shfl_xor_sync(0xFFFFFFFF, m1, 2));

            const float mn0 = fmaxf(mrun0, m0);
            const float mn1 = fmaxf(mrun1, m1);
            const float corr0 = exp2f(mrun0 - mn0);
            const float corr1 = exp2f(mrun1 - mn1);
            mrun0 = mn0; mrun1 = mn1;
            #pragma unroll
            for (int nt = 0; nt < 7; nt++) {
                ctxa[nt][0] *= corr0; ctxa[nt][1] *= corr0;
                ctxa[nt][2] *= corr1; ctxa[nt][3] *= corr1;
            }

            #pragma unroll
            for (int ck = 0; ck < 4; ck++) {
                uint32_t pa[4];
                pa[0] = h2exp2(packh2(sc[2*ck][0]   - mn0, sc[2*ck][1]   - mn0));
                pa[1] = h2exp2(packh2(sc[2*ck][2]   - mn1, sc[2*ck][3]   - mn1));
                pa[2] = h2exp2(packh2(sc[2*ck+1][0] - mn0, sc[2*ck+1][1] - mn0));
                pa[3] = h2exp2(packh2(sc[2*ck+1][2] - mn1, sc[2*ck+1][3] - mn1));
                const uint32_t vck = vbuf + ck * (16 * VHP * 2);
                #pragma unroll
                for (int t = 0; t < 3; t++) {
                    uint32_t b0, b1, b2, b3;
                    ldsm_x4_trans(b0, b1, b2, b3, vck + t * 32);
                    uint32_t f0[2] = { b0, b1 };
                    uint32_t f1[2] = { b2, b3 };
                    mma_f16(ctxa[2 * t],     pa, f0);
                    mma_f16(ctxa[2 * t + 1], pa, f1);
                }
                {
                    uint32_t b0, b1, b2, b3;
                    ldsm_x4_trans(b0, b1, b2, b3, vck + 3 * 32);
                    uint32_t f0[2] = { b0, b1 };
                    mma_f16(ctxa[6], pa, f0);
                }
            }
        }

        buf = nbuf;
        nbuf = (nbuf == NBUF - 1) ? 0 : nbuf + 1;
    }

    const float l0 = __shfl_sync(0xFFFFFFFF, ctxa[6][0], lane & 28);
    const float l1 = __shfl_sync(0xFFFFFFFF, ctxa[6][2], lane & 28);
    const float inv0 = 1.0f / l0;
    const float inv1 = 1.0f / l1;

    const int srow0 = qt * 128 + r0 + g;
    __half* out0 = ctx + ((size_t)b * S + srow0)     * DIM + h * DK;
    __half* out1 = ctx + ((size_t)b * S + srow0 + 8) * DIM + h * DK;
    #pragma unroll
    for (int nt = 0; nt < 6; nt++) {
        const int col = nt * 8 + 2 * tig;
        *(uint32_t*)(out0 + col) = packh2(ctxa[nt][0] * inv0, ctxa[nt][1] * inv0);
        *(uint32_t*)(out1 + col) = packh2(ctxa[nt][2] * inv1, ctxa[nt][3] * inv1);
    }
}

// ---------------------------------------------------------------------------
extern "C" void kernel_launch(void* const* d_in, const int* in_sizes, int n_in,
                              void* d_out, int out_size)
{
    const float* x  = (const float*)d_in[0];
    const float* Wq = (const float*)d_in[1];
    const float* bq = (const float*)d_in[2];
    const float* Wk = (const float*)d_in[3];
    const float* bk = (const float*)d_in[4];
    const float* Wv = (const float*)d_in[5];
    const float* bv = (const float*)d_in[6];
    const float* Wo = (const float*)d_in[7];
    const float* bo = (const float*)d_in[8];
    float* out = (float*)d_out;

    __half *q, *k, *v, *ctx, *cvt;
    cudaGetSymbolAddress((void**)&q,   g_q);
    cudaGetSymbolAddress((void**)&k,   g_k);
    cudaGetSymbolAddress((void**)&v,   g_v);
    cudaGetSymbolAddress((void**)&ctx, g_ctx);
    cudaGetSymbolAddress((void**)&cvt, g_cvt);

    const __half* xc  = cvt;
    const __half* Wqc = cvt + XC_ELEMS;
    const __half* Wkc = cvt + XC_ELEMS + WC_ELEMS;
    const __half* Wvc = cvt + XC_ELEMS + 2 * WC_ELEMS;
    const __half* Woc = cvt + XC_ELEMS + 3 * WC_ELEMS;

    cudaFuncSetAttribute(gemm_pipe_kernel<true>,
                         cudaFuncAttributeMaxDynamicSharedMemorySize, GEMM_SMEM_BYTES);
    cudaFuncSetAttribute(gemm_pipe_kernel<false>,
                         cudaFuncAttributeMaxDynamicSharedMemorySize, GEMM_SMEM_BYTES);
    cudaFuncSetAttribute(attention_mma_kernel,
                         cudaFuncAttributeMaxDynamicSharedMemorySize, ATT_SMEM_BYTES);

    // (1/sqrt(48)) * log2(e): scores emerge in log2 domain
    const float qscale = 0.14433756729740643f * 1.4426950408889634f;

    // Pre-convert x + all weights to fp16
    convert_f16_kernel<<<1184, 256>>>(x, Wq, Wk, Wv, Wo, (uint32_t*)cvt);

    // Fused Q/K/V projections: one launch, 18x32 = 576 blocks (128-col tiles)
    dim3 qkv_grid(18, MROWS / 128);
    gemm_pipe_kernel<true><<<qkv_grid, 256, GEMM_SMEM_BYTES>>>(
        xc, Wqc, bq, q, Wkc, bk, k, Wvc, bv, v, MROWS, DIM, DIM, qscale);

    // Attention
    dim3 agrd(S / 128, HEADS, B);                // (16, 16, 2)
    attention_mma_kernel<<<agrd, 256, ATT_SMEM_BYTES>>>(q, k, v, ctx);

    // Output projection
    dim3 o_grid(DIM / 128, MROWS / 128);         // (6, 32)
    gemm_pipe_kernel<false><<<o_grid, 256, GEMM_SMEM_BYTES>>>(
        ctx, Woc, bo, out, nullptr, nullptr, nullptr,
        nullptr, nullptr, nullptr, MROWS, DIM, DIM, 1.0f);
}

// round 17
// speedup vs baseline: 1.1722x; 1.0275x over previous
#include <cuda_runtime.h>
#include <cuda_fp16.h>
#include <math.h>
#include <stdint.h>

#define DIM   768
#define HEADS 16
#define DK    48
#define B     2
#define S     2048
#define MROWS (B * S)          // 4096

// Scratch (static device globals — no runtime allocation)
__device__ __half g_q[B * HEADS * S * DK];    // fp16, pre-scaled (1/sqrt(dk))*log2(e)
__device__ __half g_k[B * HEADS * S * DK];    // fp16
__device__ __half g_v[B * HEADS * S * DK];    // fp16
__device__ __half g_ctx[MROWS * DIM];         // fp16 attention output

#define XC_ELEMS (MROWS * DIM)                // 3145728
#define WC_ELEMS (DIM * DIM)                  // 589824
__device__ __half g_cvt[XC_ELEMS + 4 * WC_ELEMS];  // fp16 x | Wq | Wk | Wv | Wo

// ---------------------------------------------------------------------------
// helpers
// ---------------------------------------------------------------------------
__device__ __forceinline__ uint32_t packh2(float lo, float hi) {
    __half2 h = __floats2half2_rn(lo, hi);
    return *reinterpret_cast<uint32_t*>(&h);
}

__device__ __forceinline__ uint32_t h2exp2(uint32_t x) {
    uint32_t r;
    asm("ex2.approx.f16x2 %0, %1;" : "=r"(r) : "r"(x));
    return r;
}

__device__ __forceinline__ void mma_f16(float c[4],
                                        const uint32_t a[4],
                                        const uint32_t b[2]) {
    asm volatile(
        "mma.sync.aligned.m16n8k16.row.col.f32.f16.f16.f32 "
        "{%0,%1,%2,%3}, {%4,%5,%6,%7}, {%8,%9}, {%0,%1,%2,%3};\n"
        : "+f"(c[0]), "+f"(c[1]), "+f"(c[2]), "+f"(c[3])
        : "r"(a[0]), "r"(a[1]), "r"(a[2]), "r"(a[3]),
          "r"(b[0]), "r"(b[1]));
}

__device__ __forceinline__ void ldsm_x4(uint32_t& r0, uint32_t& r1,
                                        uint32_t& r2, uint32_t& r3,
                                        uint32_t saddr) {
    asm volatile(
        "ldmatrix.sync.aligned.m8n8.x4.shared.b16 {%0,%1,%2,%3}, [%4];"
        : "=r"(r0), "=r"(r1), "=r"(r2), "=r"(r3) : "r"(saddr));
}

__device__ __forceinline__ void ldsm_x4_trans(uint32_t& r0, uint32_t& r1,
                                              uint32_t& r2, uint32_t& r3,
                                              uint32_t saddr) {
    asm volatile(
        "ldmatrix.sync.aligned.m8n8.x4.trans.shared.b16 {%0,%1,%2,%3}, [%4];"
        : "=r"(r0), "=r"(r1), "=r"(r2), "=r"(r3) : "r"(saddr));
}

__device__ __forceinline__ void cp_async16(uint32_t saddr, const void* gptr) {
    asm volatile("cp.async.cg.shared.global [%0], [%1], 16;"
                 :: "r"(saddr), "l"(gptr));
}
__device__ __forceinline__ void cp_commit() {
    asm volatile("cp.async.commit_group;");
}
template <int N>
__device__ __forceinline__ void cp_wait() {
    asm volatile("cp.async.wait_group %0;" :: "n"(N));
}

// ---------------------------------------------------------------------------
// Elementwise fp16 pre-conversion: x, Wq, Wk, Wv, Wo -> g_cvt
// ---------------------------------------------------------------------------
__global__ __launch_bounds__(256)
void convert_f16_kernel(const float* __restrict__ x,
                        const float* __restrict__ Wq,
                        const float* __restrict__ Wk,
                        const float* __restrict__ Wv,
                        const float* __restrict__ Wo,
                        uint32_t* __restrict__ out)
{
    const int total8 = (XC_ELEMS + 4 * WC_ELEMS) / 8;
    for (int i = blockIdx.x * blockDim.x + threadIdx.x; i < total8;
         i += gridDim.x * blockDim.x) {
        const int e = i * 8;
        const float* src;
        if (e < XC_ELEMS) {
            src = x + e;
        } else {
            const int r = e - XC_ELEMS;
            const int w = r / WC_ELEMS;
            const int off = r % WC_ELEMS;
            src = (w == 0 ? Wq : w == 1 ? Wk : w == 2 ? Wv : Wo) + off;
        }
        float4 v0 = *(const float4*)src;
        float4 v1 = *(const float4*)(src + 4);
        uint4 u;
        u.x = packh2(v0.x, v0.y);
        u.y = packh2(v0.z, v0.w);
        u.z = packh2(v1.x, v1.y);
        u.w = packh2(v1.z, v1.w);
        *(uint4*)(out + e / 2) = u;
    }
}

// ---------------------------------------------------------------------------
// Pipelined fp16 tensor-core GEMM: out = A[M,K] @ W[N,K]^T + bias[N]
// Block tile 128xBN (BN = 64 or 128), BK=32 halfs, 8 warps as 4x2
// (warp tile 32 x BN/2). 4-stage cp.async ring, prefetch depth 2, one
// __syncthreads per slab. Pitch 40 halfs.
//   BN=128: 81920B smem, 2 CTAs/SM — for the fused QKV launch (576 blocks)
//   BN=64 : 61440B smem, 3 CTAs/SM — for the output launch (384 blocks)
// FUSED=true : blockIdx.x/(DIM/BN) -> segment 0:q(*qscale) 1:k 2:v, fp16
//              scatter to [B,HEADS,S,DK].
// FUSED=false: plain fp32 out [M,N].
// ---------------------------------------------------------------------------
#define BKH 32
#define APH 40
#define A_BYTES (128 * APH * 2)      // 10240
#define NSTAGE 4

template <bool FUSED, int BN>
__global__ __launch_bounds__(256, (BN == 128) ? 2 : 3)
void gemm_pipe_kernel(const __half* __restrict__ A,
                      const __half* __restrict__ W0, const float* __restrict__ b0,
                      void* __restrict__ o0,
                      const __half* __restrict__ W1, const float* __restrict__ b1,
                      void* __restrict__ o1,
                      const __half* __restrict__ W2, const float* __restrict__ b2,
                      void* __restrict__ o2,
                      int M, int N, int K, float qscale)
{
    constexpr int B_BYTES = BN * APH * 2;
    constexpr int NTN = BN / 16;             // n-tiles per warp (4 or 8)
    constexpr int NBX = DIM / BN;            // N-blocks per segment

    extern __shared__ uint32_t smem[];

    const int tid  = threadIdx.x;
    const int lane = tid & 31;
    const int warp = tid >> 5;
    const int warpM = warp >> 1;             // 0..3
    const int warpN = warp & 1;              // 0..1
    const int g   = lane >> 2;
    const int tig = lane & 3;
    const int mi  = lane >> 3;
    const int ri  = lane & 7;

    int seg = 0, bnx = blockIdx.x;
    const __half* W = W0; const float* bias = b0; void* out = o0;
    if (FUSED) {
        seg = blockIdx.x / NBX;
        bnx = blockIdx.x % NBX;
        if (seg == 1)      { W = W1; bias = b1; out = o1; }
        else if (seg == 2) { W = W2; bias = b2; out = o2; }
    }

    const int bm = blockIdx.y * 128;
    const int bn = bnx * BN;

    // gmem->smem staging index: j -> (row = j/4, col8 = (j%4)*8)
    const int lrA = tid >> 1;                // 0..127 (A rows, 2 uint4/thread)
    const int lkA = (tid & 1) * 16;

    const __half* Aptr = A + (size_t)(bm + lrA) * K + lkA;

    const int arow = warpM * 32;
    const int bcol = warpN * (BN / 2);

    const uint32_t as_sb = (uint32_t)__cvta_generic_to_shared(smem);
    const uint32_t bs_sb = as_sb + NSTAGE * A_BYTES;
    const uint32_t aaddr0 = as_sb +
        ((arow + (mi & 1) * 8 + ri) * APH + (mi >> 1) * 8) * 2;
    const uint32_t baddr0 = bs_sb +
        ((bcol + (mi >> 1) * 8 + ri) * APH + (mi & 1) * 8) * 2;

    // B staging mapping (BN rows x 4 uint4): BN=64 -> 1/thread, BN=128 -> 2/thread
    const int lrB = (BN == 64) ? (tid >> 2) : (tid >> 1);
    const int lkB = (BN == 64) ? ((tid & 3) * 8) : ((tid & 1) * 16);
    const __half* Wptr = W + (size_t)(bn + lrB) * K + lkB;

    auto stage = [&](int s, int buf) {
        const __half* ap = Aptr + s * BKH;
        #pragma unroll
        for (int i = 0; i < 2; i++)
            cp_async16(as_sb + (uint32_t)buf * A_BYTES +
                           (lrA * APH + lkA + i * 8) * 2,
                       ap + i * 8);
        const __half* wp = Wptr + s * BKH;
        if (BN == 64) {
            cp_async16(bs_sb + (uint32_t)buf * B_BYTES + (lrB * APH + lkB) * 2, wp);
        } else {
            #pragma unroll
            for (int i = 0; i < 2; i++)
                cp_async16(bs_sb + (uint32_t)buf * B_BYTES +
                               (lrB * APH + lkB + i * 8) * 2,
                           wp + i * 8);
        }
    };

    float c[2][NTN][4];
    #pragma unroll
    for (int mt = 0; mt < 2; mt++)
        #pragma unroll
        for (int nt = 0; nt < NTN; nt++)
            #pragma unroll
            for (int i = 0; i < 4; i++) c[mt][nt][i] = 0.0f;

    const int NS = K / BKH;      // 24 slabs
    stage(0, 0); cp_commit();
    stage(1, 1); cp_commit();
    stage(2, 2); cp_commit();

    for (int s = 0; s < NS; s++) {
        if (s + 2 < NS)      cp_wait<2>();
        else if (s + 1 < NS) cp_wait<1>();
        else                 cp_wait<0>();
        __syncthreads();
        if (s + 3 < NS) { stage(s + 3, (s + 3) & 3); cp_commit(); }

        const int buf = s & 3;
        const uint32_t abuf = aaddr0 + (uint32_t)buf * A_BYTES;
        const uint32_t bbuf = baddr0 + (uint32_t)buf * B_BYTES;
        #pragma unroll
        for (int ks = 0; ks < 2; ks++) {
            const uint32_t koff = ks * 32;           // 16 halfs
            uint32_t afr[2][4], bfr[NTN][2];
            #pragma unroll
            for (int mt = 0; mt < 2; mt++)
                ldsm_x4(afr[mt][0], afr[mt][1], afr[mt][2], afr[mt][3],
                        abuf + mt * (16 * APH * 2) + koff);
            #pragma unroll
            for (int p = 0; p < NTN / 2; p++)
                ldsm_x4(bfr[2*p][0], bfr[2*p][1], bfr[2*p+1][0], bfr[2*p+1][1],
                        bbuf + p * (16 * APH * 2) + koff);
            #pragma unroll
            for (int mt = 0; mt < 2; mt++)
                #pragma unroll
                for (int nt = 0; nt < NTN; nt++)
                    mma_f16(c[mt][nt], afr[mt], bfr[nt]);
        }
    }

    // ---- epilogue ----
    #pragma unroll
    for (int mt = 0; mt < 2; mt++) {
        #pragma unroll
        for (int nt = 0; nt < NTN; nt++) {
            #pragma unroll
            for (int i = 0; i < 4; i++) {
                const int m = bm + arow + mt * 16 + g + (i >> 1) * 8;
                const int n = bn + bcol + nt * 8 + 2 * tig + (i & 1);
                const float v = c[mt][nt][i] + bias[n];
                if (!FUSED) {
                    ((float*)out)[(size_t)m * N + n] = v;
                } else {
                    const int bidx = m / S;
                    const int s_   = m % S;
                    const int h    = n / DK;
                    const int d    = n % DK;
                    const size_t idx = (((size_t)bidx * HEADS + h) * S + s_) * DK + d;
                    const float sv = (seg == 0) ? v * qscale : v;
                    ((__half*)out)[idx] = __float2half_rn(sv);
                }
            }
        }
    }
}

// ---------------------------------------------------------------------------
// fp16 tensor-core flash attention (FROZEN at round-15 config):
// softmax-lite, 128-key staging tiles, 3-buffer ring, single barrier/tile,
// log2-domain scores + ex2.approx.f16x2, ones-column row sums in the mma.
// ---------------------------------------------------------------------------
#define KPH 56
#define PPH 56
#define VHP 56
#define TKEYS 128
#define KB_BYTES (TKEYS * KPH * 2)       // 14336
#define VB_BYTES (TKEYS * VHP * 2)       // 14336
#define PS_BYTES (128 * PPH * 2)         // 14336
#define NBUF 3
#define CHUNK_BYTES (64 * KPH * 2)       // 7168
#define ATT_SMEM_BYTES (NBUF * (KB_BYTES + VB_BYTES) + PS_BYTES)   // 100352

__global__ __launch_bounds__(256)
void attention_mma_kernel(const __half* __restrict__ Q,
                          const __half* __restrict__ K,
                          const __half* __restrict__ Vf,
                          __half* __restrict__ ctx)
{
    extern __shared__ uint32_t sm[];

    const int qt   = blockIdx.x;
    const int h    = blockIdx.y;
    const int b    = blockIdx.z;
    const int tid  = threadIdx.x;
    const int lane = tid & 31;
    const int warp = tid >> 5;
    const int g    = lane >> 2;
    const int tig  = lane & 3;
    const int mi   = lane >> 3;
    const int ri   = lane & 7;
    const int r0   = warp * 16;

    const size_t head_off = ((size_t)b * HEADS + h) * S * DK;

    const uint32_t base_sb = (uint32_t)__cvta_generic_to_shared(sm);
    const uint32_t ks_sb = base_sb;
    const uint32_t vh_sb = base_sb + NBUF * KB_BYTES;
    const uint32_t ps_sb = base_sb + NBUF * (KB_BYTES + VB_BYTES);
    __half* Vsh = (__half*)((char*)sm + NBUF * KB_BYTES);
    __half* Psh = (__half*)((char*)sm + NBUF * (KB_BYTES + VB_BYTES));

    const uint32_t kaddr = ks_sb + (((mi >> 1) * 8 + ri) * KPH + (mi & 1) * 8) * 2;
    const uint32_t paddr = ps_sb + ((r0 + (mi & 1) * 8 + ri) * PPH + (mi >> 1) * 8) * 2;
    const uint32_t vaddr = vh_sb + (((mi & 1) * 8 + ri) * VHP + (mi >> 1) * 8) * 2;

    const __half* kg = K + head_off;
    const __half* vg = Vf + head_off;

    auto stage_tile = [&](int kt, int bufsel) {
        const __half* ksrc = kg + (size_t)kt * TKEYS * DK;
        #pragma unroll
        for (int i = tid; i < TKEYS * 6; i += 256) {
            const int row = i / 6, c8 = (i % 6) * 8;
            cp_async16(ks_sb + (uint32_t)bufsel * KB_BYTES + (row * KPH + c8) * 2,
                       ksrc + row * DK + c8);
        }
        const __half* vsrc = vg + (size_t)kt * TKEYS * DK;
        #pragma unroll
        for (int i = tid; i < TKEYS * 6; i += 256) {
            const int row = i / 6, c8 = (i % 6) * 8;
            cp_async16(vh_sb + (uint32_t)bufsel * VB_BYTES + (row * VHP + c8) * 2,
                       vsrc + row * DK + c8);
        }
    };

    stage_tile(0, 0);
    cp_commit();

    {
        const uint4* qsrc = (const uint4*)(Q + head_off + (size_t)qt * 128 * DK);
        #pragma unroll
        for (int i = tid; i < 768; i += 256) {
            const int row = i / 6, c8 = (i % 6) * 8;
            *(uint4*)&Psh[row * PPH + c8] = qsrc[i];
        }
        for (int i = tid; i < TKEYS * NBUF; i += 256) {
            const int bsel = i / TKEYS, row = i % TKEYS;
            uint4 ones = { 0x00003C00u, 0u, 0u, 0u };   // {1.0h, 0...}
            *(uint4*)&Vsh[bsel * (VB_BYTES / 2) + row * VHP + 48] = ones;
        }
    }
    __syncthreads();

    uint32_t qf[3][4];
    #pragma unroll
    for (int ks = 0; ks < 3; ks++)
        ldsm_x4(qf[ks][0], qf[ks][1], qf[ks][2], qf[ks][3], paddr + ks * 32);

    float ctxa[7][4];
    #pragma unroll
    for (int nt = 0; nt < 7; nt++)
        #pragma unroll
        for (int i = 0; i < 4; i++) ctxa[nt][i] = 0.0f;
    float mrun0 = -INFINITY, mrun1 = -INFINITY;

    const int NT = S / TKEYS;
    int buf = 0, nbuf = 1;
    for (int kt = 0; kt < NT; kt++) {
        if (kt + 1 < NT) {
            stage_tile(kt + 1, nbuf);
            cp_commit();
            cp_wait<1>();
        } else {
            cp_wait<0>();
        }
        __syncthreads();

        #pragma unroll
        for (int ch = 0; ch < 2; ch++) {
            const uint32_t kbuf = kaddr + (uint32_t)buf * KB_BYTES + ch * CHUNK_BYTES;
            const uint32_t vbuf = vaddr + (uint32_t)buf * VB_BYTES + ch * CHUNK_BYTES;

            float sc[8][4];
            #pragma unroll
            for (int nt = 0; nt < 8; nt++)
                #pragma unroll
                for (int i = 0; i < 4; i++) sc[nt][i] = 0.0f;

            #pragma unroll
            for (int ks = 0; ks < 3; ks++) {
                const uint32_t ka = kbuf + ks * 32;
                #pragma unroll
                for (int p = 0; p < 4; p++) {
                    uint32_t b0, b1, b2, b3;
                    ldsm_x4(b0, b1, b2, b3, ka + p * (16 * KPH * 2));
                    uint32_t f0[2] = { b0, b1 };
                    uint32_t f1[2] = { b2, b3 };
                    mma_f16(sc[2 * p],     qf[ks], f0);
                    mma_f16(sc[2 * p + 1], qf[ks], f1);
                }
            }

            float m0 = sc[0][0], m1 = sc[0][2];
            #pragma unroll
            for (int nt = 0; nt < 8; nt++) {
                m0 = fmaxf(m0, fmaxf(sc[nt][0], sc[nt][1]));
                m1 = fmaxf(m1, fmaxf(sc[nt][2], sc[nt][3]));
            }
            m0 = fmaxf(m0, __shfl_xor_sync(0xFFFFFFFF, m0, 1));
            m0 = fmaxf(m0, __shfl_xor_sync(0xFFFFFFFF, m0, 2));
            m1 = fmaxf(m1, __shfl_xor_sync(0xFFFFFFFF, m1, 1));
            m1 = fmaxf(m1, __shfl_xor_sync(0xFFFFFFFF, m1, 2));

            const float mn0 = fmaxf(mrun0, m0);
            const float mn1 = fmaxf(mrun1, m1);
            const float corr0 = exp2f(mrun0 - mn0);
            const float corr1 = exp2f(mrun1 - mn1);
            mrun0 = mn0; mrun1 = mn1;
            #pragma unroll
            for (int nt = 0; nt < 7; nt++) {
                ctxa[nt][0] *= corr0; ctxa[nt][1] *= corr0;
                ctxa[nt][2] *= corr1; ctxa[nt][3] *= corr1;
            }

            #pragma unroll
            for (int ck = 0; ck < 4; ck++) {
                uint32_t pa[4];
                pa[0] = h2exp2(packh2(sc[2*ck][0]   - mn0, sc[2*ck][1]   - mn0));
                pa[1] = h2exp2(packh2(sc[2*ck][2]   - mn1, sc[2*ck][3]   - mn1));
                pa[2] = h2exp2(packh2(sc[2*ck+1][0] - mn0, sc[2*ck+1][1] - mn0));
                pa[3] = h2exp2(packh2(sc[2*ck+1][2] - mn1, sc[2*ck+1][3] - mn1));
                const uint32_t vck = vbuf + ck * (16 * VHP * 2);
                #pragma unroll
                for (int t = 0; t < 3; t++) {
                    uint32_t b0, b1, b2, b3;
                    ldsm_x4_trans(b0, b1, b2, b3, vck + t * 32);
                    uint32_t f0[2] = { b0, b1 };
                    uint32_t f1[2] = { b2, b3 };
                    mma_f16(ctxa[2 * t],     pa, f0);
                    mma_f16(ctxa[2 * t + 1], pa, f1);
                }
                {
                    uint32_t b0, b1, b2, b3;
                    ldsm_x4_trans(b0, b1, b2, b3, vck + 3 * 32);
                    uint32_t f0[2] = { b0, b1 };
                    mma_f16(ctxa[6], pa, f0);
                }
            }
        }

        buf = nbuf;
        nbuf = (nbuf == NBUF - 1) ? 0 : nbuf + 1;
    }

    const float l0 = __shfl_sync(0xFFFFFFFF, ctxa[6][0], lane & 28);
    const float l1 = __shfl_sync(0xFFFFFFFF, ctxa[6][2], lane & 28);
    const float inv0 = 1.0f / l0;
    const float inv1 = 1.0f / l1;

    const int srow0 = qt * 128 + r0 + g;
    __half* out0 = ctx + ((size_t)b * S + srow0)     * DIM + h * DK;
    __half* out1 = ctx + ((size_t)b * S + srow0 + 8) * DIM + h * DK;
    #pragma unroll
    for (int nt = 0; nt < 6; nt++) {
        const int col = nt * 8 + 2 * tig;
        *(uint32_t*)(out0 + col) = packh2(ctxa[nt][0] * inv0, ctxa[nt][1] * inv0);
        *(uint32_t*)(out1 + col) = packh2(ctxa[nt][2] * inv1, ctxa[nt][3] * inv1);
    }
}

// ---------------------------------------------------------------------------
extern "C" void kernel_launch(void* const* d_in, const int* in_sizes, int n_in,
                              void* d_out, int out_size)
{
    const float* x  = (const float*)d_in[0];
    const float* Wq = (const float*)d_in[1];
    const float* bq = (const float*)d_in[2];
    const float* Wk = (const float*)d_in[3];
    const float* bk = (const float*)d_in[4];
    const float* Wv = (const float*)d_in[5];
    const float* bv = (const float*)d_in[6];
    const float* Wo = (const float*)d_in[7];
    const float* bo = (const float*)d_in[8];
    float* out = (float*)d_out;

    __half *q, *k, *v, *ctx, *cvt;
    cudaGetSymbolAddress((void**)&q,   g_q);
    cudaGetSymbolAddress((void**)&k,   g_k);
    cudaGetSymbolAddress((void**)&v,   g_v);
    cudaGetSymbolAddress((void**)&ctx, g_ctx);
    cudaGetSymbolAddress((void**)&cvt, g_cvt);

    const __half* xc  = cvt;
    const __half* Wqc = cvt + XC_ELEMS;
    const __half* Wkc = cvt + XC_ELEMS + WC_ELEMS;
    const __half* Wvc = cvt + XC_ELEMS + 2 * WC_ELEMS;
    const __half* Woc = cvt + XC_ELEMS + 3 * WC_ELEMS;

    const int qkv_smem = NSTAGE * (A_BYTES + 128 * APH * 2);   // 81920
    const int out_smem = NSTAGE * (A_BYTES + 64 * APH * 2);    // 61440
    cudaFuncSetAttribute((gemm_pipe_kernel<true, 128>),
                         cudaFuncAttributeMaxDynamicSharedMemorySize, qkv_smem);
    cudaFuncSetAttribute((gemm_pipe_kernel<false, 64>),
                         cudaFuncAttributeMaxDynamicSharedMemorySize, out_smem);
    cudaFuncSetAttribute(attention_mma_kernel,
                         cudaFuncAttributeMaxDynamicSharedMemorySize, ATT_SMEM_BYTES);

    // (1/sqrt(48)) * log2(e): scores emerge in log2 domain
    const float qscale = 0.14433756729740643f * 1.4426950408889634f;

    // Pre-convert x + all weights to fp16
    convert_f16_kernel<<<1184, 256>>>(x, Wq, Wk, Wv, Wo, (uint32_t*)cvt);

    // Fused Q/K/V projections: one launch, 18x32 = 576 blocks (128-col tiles)
    dim3 qkv_grid(18, MROWS / 128);
    gemm_pipe_kernel<true, 128><<<qkv_grid, 256, qkv_smem>>>(
        xc, Wqc, bq, q, Wkc, bk, k, Wvc, bv, v, MROWS, DIM, DIM, qscale);

    // Attention
    dim3 agrd(S / 128, HEADS, B);                // (16, 16, 2)
    attention_mma_kernel<<<agrd, 256, ATT_SMEM_BYTES>>>(q, k, v, ctx);

    // Output projection: 64-col tiles, 12x32 = 384 blocks, 3 CTAs/SM
    dim3 o_grid(DIM / 64, MROWS / 128);          // (12, 32)
    gemm_pipe_kernel<false, 64><<<o_grid, 256, out_smem>>>(
        ctx, Woc, bo, out, nullptr, nullptr, nullptr,
        nullptr, nullptr, nullptr, MROWS, DIM, DIM, 1.0f);
}